// round 5
// baseline (speedup 1.0000x reference)
#include <cuda_runtime.h>

#define SIDES 2
#define NB 8
#define CC 64
#define HWP 65536
#define EPSV 1e-5f
#define TP1 128
#define TP3 4096

typedef unsigned long long u64;
typedef unsigned int u32;

// ---- scratch (device globals; no runtime allocation) ----
__device__ float g_v[(size_t)SIDES * NB * CC * HWP];   // materialized val tensors (268MB)
__device__ float g_klog[(size_t)SIDES * NB * HWP];     // key logits (post-silu), 4MB
__device__ float g_sumx[SIDES * NB * CC];
__device__ u32   g_xcmax[SIDES * NB * CC];             // encoded float max
__device__ u32   g_keymax[SIDES * NB];
__device__ float g_Z[SIDES * NB];
__device__ float g_feanum[SIDES * NB * CC];
__device__ float g_avg[SIDES * NB * CC];
__device__ float g_mx[SIDES * NB * CC];
__device__ float g_gate[SIDES * NB * CC];

// ---- helpers ----
__device__ __forceinline__ u32 fenc(float f) {
    u32 u = __float_as_uint(f);
    return (u & 0x80000000u) ? ~u : (u | 0x80000000u);
}
__device__ __forceinline__ float fdec(u32 u) {
    return __uint_as_float((u & 0x80000000u) ? (u & 0x7fffffffu) : ~u);
}
__device__ __forceinline__ float siluf(float x) { return x / (1.f + __expf(-x)); }

__device__ __forceinline__ u64 pack2(float x, float y) {
    u64 r; asm("mov.b64 %0,{%1,%2};" : "=l"(r) : "f"(x), "f"(y)); return r;
}
__device__ __forceinline__ u64 ffma2(u64 a, u64 b, u64 c) {
    u64 d; asm("fma.rn.f32x2 %0,%1,%2,%3;" : "=l"(d) : "l"(a), "l"(b), "l"(c)); return d;
}
__device__ __forceinline__ float2 unpk(u64 v) {
    float2 f; asm("mov.b64 {%0,%1},%2;" : "=f"(f.x), "=f"(f.y) : "l"(v)); return f;
}

// ---- K0: reset accumulators (must re-run every launch for graph replay) ----
__global__ void k0_init() {
    int t = threadIdx.x;
    if (t < SIDES * NB * CC) { g_sumx[t] = 0.f; g_xcmax[t] = 0x007FFFFFu; g_feanum[t] = 0.f; }
    if (t < SIDES * NB) { g_keymax[t] = 0x007FFFFFu; g_Z[t] = 0.f; }
}

// ---- K1: fused per-pixel GEMM [conv_w;val_w](128x64) x X(64xTP1) ----
// produces: g_v (silu(bn(val conv))), g_xcmax (spatial max of raw conv, bias added later),
//           g_klog + g_keymax (key logits), g_sumx (per-channel spatial sums)
__global__ void __launch_bounds__(256) k1_main(
    const float* __restrict__ rgb, const float* __restrict__ ir,
    const float* __restrict__ conv_w, const float* __restrict__ key_w,
    const float* __restrict__ val_w,
    const float* __restrict__ val_g, const float* __restrict__ val_b,
    const float* __restrict__ val_m, const float* __restrict__ val_vv,
    const float* __restrict__ key_g, const float* __restrict__ key_b,
    const float* __restrict__ key_m, const float* __restrict__ key_vv)
{
    extern __shared__ float sm[];
    float* sW  = sm;                 // [128][65] padded
    float* sX  = sm + 128 * 65;      // [64][128]
    float* sVs = sX + 64 * 128;      // [64]
    float* sVb = sVs + 64;           // [64]

    int tid = threadIdx.x;
    int s = blockIdx.z, n = blockIdx.y;
    int p0 = blockIdx.x * TP1;
    int sn = s * NB + n;
    const float* xb = (s ? ir : rgb) + (size_t)n * CC * HWP;

    for (int idx = tid; idx < 128 * 64; idx += 256) {
        int o = idx >> 6, c = idx & 63;
        sW[o * 65 + c] = (o < 64) ? conv_w[o * 64 + c] : val_w[(o - 64) * 64 + c];
    }
    if (tid < 64) {
        float sc = val_g[tid] * rsqrtf(val_vv[tid] + EPSV);
        sVs[tid] = sc;
        sVb[tid] = val_b[tid] - val_m[tid] * sc;
    }
    for (int idx = tid; idx < 64 * 32; idx += 256) {
        int c = idx >> 5, i = idx & 31;
        float4 v = *(const float4*)(xb + (size_t)c * HWP + p0 + i * 4);
        *(float4*)(sX + c * 128 + i * 4) = v;
    }
    __syncthreads();

    int to = tid >> 4, tp = tid & 15;
    u64 acc[8][4];
#pragma unroll
    for (int i = 0; i < 8; i++)
#pragma unroll
        for (int j = 0; j < 4; j++) acc[i][j] = 0ull;

    const u64* sX2 = (const u64*)sX;   // float2 view, 64 per row
#pragma unroll 4
    for (int c = 0; c < 64; c++) {
        u64 xa0 = sX2[c * 64 + tp];
        u64 xa1 = sX2[c * 64 + tp + 16];
        u64 xa2 = sX2[c * 64 + tp + 32];
        u64 xa3 = sX2[c * 64 + tp + 48];
        const float* wc = sW + (to * 8) * 65 + c;
#pragma unroll
        for (int i = 0; i < 8; i++) {
            float w = wc[i * 65];
            u64 w2 = pack2(w, w);
            acc[i][0] = ffma2(w2, xa0, acc[i][0]);
            acc[i][1] = ffma2(w2, xa1, acc[i][1]);
            acc[i][2] = ffma2(w2, xa2, acc[i][2]);
            acc[i][3] = ffma2(w2, xa3, acc[i][3]);
        }
    }

    if (to < 8) {  // conv rows: spatial max (bias added in K2)
#pragma unroll
        for (int i = 0; i < 8; i++) {
            int o = to * 8 + i;
            float m = -3.4e38f;
#pragma unroll
            for (int j = 0; j < 4; j++) {
                float2 f = unpk(acc[i][j]);
                m = fmaxf(m, fmaxf(f.x, f.y));
            }
#pragma unroll
            for (int d = 8; d; d >>= 1) m = fmaxf(m, __shfl_xor_sync(0xffffffffu, m, d));
            if (tp == 0) atomicMax(&g_xcmax[sn * CC + o], fenc(m));
        }
    } else {       // val rows: bn + silu + store
#pragma unroll
        for (int i = 0; i < 8; i++) {
            int o = (to - 8) * 8 + i;
            float sc = sVs[o], sh = sVb[o];
            float2* dst = (float2*)(g_v + ((size_t)sn * CC + o) * HWP + p0);
#pragma unroll
            for (int j = 0; j < 4; j++) {
                float2 f = unpk(acc[i][j]);
                f.x = siluf(fmaf(f.x, sc, sh));
                f.y = siluf(fmaf(f.y, sc, sh));
                dst[tp + 16 * j] = f;
            }
        }
    }

    // key logits: one pixel per thread (tid < 128)
    if (tid < TP1) {
        float kscale = key_g[0] * rsqrtf(key_vv[0] + EPSV);
        float kshift = key_b[0] - key_m[0] * kscale;
        float a = 0.f;
#pragma unroll 8
        for (int c = 0; c < 64; c++) a = fmaf(key_w[c], sX[c * 128 + tid], a);
        float kl = siluf(fmaf(a, kscale, kshift));
        g_klog[(size_t)sn * HWP + p0 + tid] = kl;
        float km = kl;
#pragma unroll
        for (int d = 16; d; d >>= 1) km = fmaxf(km, __shfl_xor_sync(0xffffffffu, km, d));
        if ((tid & 31) == 0) atomicMax(&g_keymax[sn], fenc(km));
    }
    // per-channel spatial sums (rotated to avoid bank conflicts)
    if (tid < 64) {
        float a = 0.f;
        for (int j = 0; j < 128; j++) a += sX[tid * 128 + ((tid + j) & 127)];
        atomicAdd(&g_sumx[sn * CC + tid], a);
    }
}

// ---- K2: channel softmaxes for avg and max paths ----
__global__ void k2_avgmax(const float* __restrict__ conv_w, const float* __restrict__ conv_b) {
    int n = blockIdx.x, s = blockIdx.y, sn = s * NB + n;
    int t = threadIdx.x;  // 64 threads
    __shared__ float red[64];
    const float inv = 1.f / (float)HWP;
    float la = conv_b[t];
    for (int c = 0; c < 64; c++) la = fmaf(conv_w[t * 64 + c], g_sumx[sn * CC + c] * inv, la);
    float lm = fdec(g_xcmax[sn * CC + t]) + conv_b[t];

    // softmax(la)
    red[t] = la; __syncthreads();
    for (int d = 32; d; d >>= 1) { if (t < d) red[t] = fmaxf(red[t], red[t + d]); __syncthreads(); }
    float M = red[0]; __syncthreads();
    float e = __expf(la - M);
    red[t] = e; __syncthreads();
    for (int d = 32; d; d >>= 1) { if (t < d) red[t] += red[t + d]; __syncthreads(); }
    g_avg[sn * CC + t] = e / red[0]; __syncthreads();

    // softmax(lm)
    red[t] = lm; __syncthreads();
    for (int d = 32; d; d >>= 1) { if (t < d) red[t] = fmaxf(red[t], red[t + d]); __syncthreads(); }
    M = red[0]; __syncthreads();
    e = __expf(lm - M);
    red[t] = e; __syncthreads();
    for (int d = 32; d; d >>= 1) { if (t < d) red[t] += red[t + d]; __syncthreads(); }
    g_mx[sn * CC + t] = e / red[0];
}

// ---- K3: key-softmax partition Z + unnormalized fea = sum_p v_other * exp(klog - max) ----
__global__ void __launch_bounds__(256) k3_fea() {
    int me = blockIdx.z, n = blockIdx.y, p0 = blockIdx.x * TP3;
    int sn = me * NB + n, on = (1 - me) * NB + n;
    int tid = threadIdx.x, lane = tid & 31, wid = tid >> 5;
    __shared__ float se[TP3];
    __shared__ float sred[8];

    float kmax = fdec(g_keymax[sn]);
    const float* kl = g_klog + (size_t)sn * HWP + p0;
    float z = 0.f;
    for (int idx = tid; idx < TP3; idx += 256) {
        float e = __expf(kl[idx] - kmax);
        se[idx] = e;
        z += e;
    }
#pragma unroll
    for (int d = 16; d; d >>= 1) z += __shfl_xor_sync(0xffffffffu, z, d);
    if (lane == 0) sred[wid] = z;
    __syncthreads();
    if (tid == 0) {
        float tt = 0.f;
        for (int i = 0; i < 8; i++) tt += sred[i];
        atomicAdd(&g_Z[sn], tt);
    }
    const float4* ef = (const float4*)se;
    for (int c = wid; c < 64; c += 8) {
        const float4* vf = (const float4*)(g_v + ((size_t)on * CC + c) * HWP + p0);
        float a = 0.f;
        for (int i = lane; i < TP3 / 4; i += 32) {
            float4 v = vf[i], e = ef[i];
            a = fmaf(v.x, e.x, fmaf(v.y, e.y, fmaf(v.z, e.z, fmaf(v.w, e.w, a))));
        }
#pragma unroll
        for (int d = 16; d; d >>= 1) a += __shfl_xor_sync(0xffffffffu, a, d);
        if (lane == 0) atomicAdd(&g_feanum[sn * CC + c], a);
    }
}

// ---- K4: gate = sigmoid(LN(fea @ convb_w^T)) ----
__global__ void k4_gate(const float* __restrict__ convb_w,
                        const float* __restrict__ ln_g, const float* __restrict__ ln_b) {
    int n = blockIdx.x, me = blockIdx.y, sn = me * NB + n;
    int t = threadIdx.x;  // 64
    __shared__ float sf[64];
    __shared__ float red[64];
    float Z = g_Z[sn];
    sf[t] = g_feanum[sn * CC + t] / Z;
    __syncthreads();
    float v = 0.f;
    for (int c = 0; c < 64; c++) v = fmaf(convb_w[t * 64 + c], sf[c], v);
    red[t] = v; __syncthreads();
    for (int d = 32; d; d >>= 1) { if (t < d) red[t] += red[t + d]; __syncthreads(); }
    float mu = red[0] * (1.f / 64.f); __syncthreads();
    float dv = v - mu;
    red[t] = dv * dv; __syncthreads();
    for (int d = 32; d; d >>= 1) { if (t < d) red[t] += red[t + d]; __syncthreads(); }
    float var = red[0] * (1.f / 64.f);
    float nrm = fmaf(dv * rsqrtf(var + EPSV), ln_g[t], ln_b[t]);
    g_gate[sn * CC + t] = 1.f / (1.f + __expf(-nrm));
}

// ---- K5: avgm/maxm mixing + half conv_block + gated residual output ----
__global__ void __launch_bounds__(256) k5_out(
    const float* __restrict__ rgb, const float* __restrict__ ir,
    const float* __restrict__ half_w, const float* __restrict__ half_g,
    const float* __restrict__ half_b, const float* __restrict__ half_m,
    const float* __restrict__ half_vv, float* __restrict__ out)
{
    int me = blockIdx.z, n = blockIdx.y, p0 = blockIdx.x * 1024;
    int sn = me * NB + n, on = (1 - me) * NB + n;
    int tid = threadIdx.x;
    __shared__ float sA[64], sM[64], sG[64];
    if (tid < 64) {
        sA[tid] = g_avg[sn * CC + tid];
        sM[tid] = g_mx[sn * CC + tid];
        sG[tid] = g_gate[sn * CC + tid];
    }
    __syncthreads();
    float h0 = half_w[0], h1 = half_w[1];
    float hsc = half_g[0] * rsqrtf(half_vv[0] + EPSV);
    float hsh = half_b[0] - half_m[0] * hsc;

    size_t pq = (size_t)(p0 + tid * 4) >> 2;   // float4 index within one HW row
    const float4* vbase = (const float4*)(g_v + (size_t)on * CC * HWP);
    float4 fa = {0.f, 0.f, 0.f, 0.f}, fm = {0.f, 0.f, 0.f, 0.f};
#pragma unroll 8
    for (int c = 0; c < 64; c++) {
        float4 v = vbase[(size_t)c * (HWP / 4) + pq];
        float a = sA[c], m = sM[c];
        fa.x = fmaf(a, v.x, fa.x); fa.y = fmaf(a, v.y, fa.y);
        fa.z = fmaf(a, v.z, fa.z); fa.w = fmaf(a, v.w, fa.w);
        fm.x = fmaf(m, v.x, fm.x); fm.y = fmaf(m, v.y, fm.y);
        fm.z = fmaf(m, v.z, fm.z); fm.w = fmaf(m, v.w, fm.w);
    }
    float4 h;
    h.x = siluf(fmaf(fmaf(h0, fa.x, h1 * fm.x), hsc, hsh));
    h.y = siluf(fmaf(fmaf(h0, fa.y, h1 * fm.y), hsc, hsh));
    h.z = siluf(fmaf(fmaf(h0, fa.z, h1 * fm.z), hsc, hsh));
    h.w = siluf(fmaf(fmaf(h0, fa.w, h1 * fm.w), hsc, hsh));

    const float4* xme = (const float4*)((me ? ir : rgb) + (size_t)n * CC * HWP);
    float4* ob = (float4*)(out + (size_t)sn * CC * HWP);
#pragma unroll 8
    for (int c = 0; c < 64; c++) {
        float4 x4 = xme[(size_t)c * (HWP / 4) + pq];
        float g = sG[c];
        float4 o4;
        o4.x = fmaf(g, h.x, x4.x);
        o4.y = fmaf(g, h.y, x4.y);
        o4.z = fmaf(g, h.z, x4.z);
        o4.w = fmaf(g, h.w, x4.w);
        ob[(size_t)c * (HWP / 4) + pq] = o4;
    }
}

extern "C" void kernel_launch(void* const* d_in, const int* in_sizes, int n_in,
                              void* d_out, int out_size) {
    const float* rgb     = (const float*)d_in[0];
    const float* ir      = (const float*)d_in[1];
    const float* conv_w  = (const float*)d_in[2];
    const float* conv_b  = (const float*)d_in[3];
    const float* key_w   = (const float*)d_in[4];
    const float* key_g   = (const float*)d_in[5];
    const float* key_b   = (const float*)d_in[6];
    const float* key_m   = (const float*)d_in[7];
    const float* key_v   = (const float*)d_in[8];
    const float* val_w   = (const float*)d_in[9];
    const float* val_g   = (const float*)d_in[10];
    const float* val_b   = (const float*)d_in[11];
    const float* val_m   = (const float*)d_in[12];
    const float* val_v   = (const float*)d_in[13];
    const float* convb_w = (const float*)d_in[14];
    const float* half_w  = (const float*)d_in[15];
    const float* half_g  = (const float*)d_in[16];
    const float* half_b  = (const float*)d_in[17];
    const float* half_m  = (const float*)d_in[18];
    const float* half_v  = (const float*)d_in[19];
    const float* ln_g    = (const float*)d_in[20];
    const float* ln_b    = (const float*)d_in[21];
    float* out = (float*)d_out;

    const int smem1 = (128 * 65 + 64 * 128 + 128) * (int)sizeof(float);  // 66560
    cudaFuncSetAttribute(k1_main, cudaFuncAttributeMaxDynamicSharedMemorySize, smem1);

    k0_init<<<1, 1024>>>();
    k1_main<<<dim3(HWP / TP1, NB, SIDES), 256, smem1>>>(
        rgb, ir, conv_w, key_w, val_w, val_g, val_b, val_m, val_v,
        key_g, key_b, key_m, key_v);
    k2_avgmax<<<dim3(NB, SIDES), 64>>>(conv_w, conv_b);
    k3_fea<<<dim3(HWP / TP3, NB, SIDES), 256>>>();
    k4_gate<<<dim3(NB, SIDES), 64>>>(convb_w, ln_g, ln_b);
    k5_out<<<dim3(HWP / 1024, NB, SIDES), 256>>>(
        rgb, ir, half_w, half_g, half_b, half_m, half_v, out);
}

// round 6
// speedup vs baseline: 1.1248x; 1.1248x over previous
#include <cuda_runtime.h>

#define SIDES 2
#define NB 8
#define CC 64
#define HWP 65536
#define EPSV 1e-5f
#define TP1 128

typedef unsigned long long u64;
typedef unsigned int u32;

// ---- scratch (device globals; no runtime allocation) ----
__device__ float g_v[(size_t)SIDES * NB * CC * HWP];   // materialized val tensors (268MB)
__device__ float g_klog[(size_t)SIDES * NB * HWP];     // key logits (post-silu), 4MB
__device__ float g_avgm[(size_t)SIDES * NB * HWP];     // per-pixel avg-mix, 4MB
__device__ float g_maxm[(size_t)SIDES * NB * HWP];     // per-pixel max-mix, 4MB
__device__ float g_sumx[SIDES * NB * CC];
__device__ u32   g_xcmax[SIDES * NB * CC];             // encoded float max
__device__ u32   g_keymax[SIDES * NB];
__device__ float g_Z[SIDES * NB];
__device__ float g_feanum[SIDES * NB * CC];
__device__ float g_avg[SIDES * NB * CC];
__device__ float g_mx[SIDES * NB * CC];
__device__ float g_gate[SIDES * NB * CC];

// ---- helpers ----
__device__ __forceinline__ u32 fenc(float f) {
    u32 u = __float_as_uint(f);
    return (u & 0x80000000u) ? ~u : (u | 0x80000000u);
}
__device__ __forceinline__ float fdec(u32 u) {
    return __uint_as_float((u & 0x80000000u) ? (u & 0x7fffffffu) : ~u);
}
__device__ __forceinline__ float siluf(float x) { return x / (1.f + __expf(-x)); }

__device__ __forceinline__ u64 pack2(float x, float y) {
    u64 r; asm("mov.b64 %0,{%1,%2};" : "=l"(r) : "f"(x), "f"(y)); return r;
}
__device__ __forceinline__ u64 ffma2(u64 a, u64 b, u64 c) {
    u64 d; asm("fma.rn.f32x2 %0,%1,%2,%3;" : "=l"(d) : "l"(a), "l"(b), "l"(c)); return d;
}
__device__ __forceinline__ float2 unpk(u64 v) {
    float2 f; asm("mov.b64 {%0,%1},%2;" : "=f"(f.x), "=f"(f.y) : "l"(v)); return f;
}

// ---- K0: reset accumulators (must re-run every launch for graph replay) ----
__global__ void k0_init() {
    int t = threadIdx.x;
    if (t < SIDES * NB * CC) { g_sumx[t] = 0.f; g_xcmax[t] = 0x007FFFFFu; g_feanum[t] = 0.f; }
    if (t < SIDES * NB) { g_keymax[t] = 0x007FFFFFu; g_Z[t] = 0.f; }
}

// ---- K1: fused per-pixel GEMM [conv_w;val_w](128x64) x X(64xTP1) ----  (UNCHANGED from R5)
__global__ void __launch_bounds__(256) k1_main(
    const float* __restrict__ rgb, const float* __restrict__ ir,
    const float* __restrict__ conv_w, const float* __restrict__ key_w,
    const float* __restrict__ val_w,
    const float* __restrict__ val_g, const float* __restrict__ val_b,
    const float* __restrict__ val_m, const float* __restrict__ val_vv,
    const float* __restrict__ key_g, const float* __restrict__ key_b,
    const float* __restrict__ key_m, const float* __restrict__ key_vv)
{
    extern __shared__ float sm[];
    float* sW  = sm;                 // [128][65] padded
    float* sX  = sm + 128 * 65;      // [64][128]
    float* sVs = sX + 64 * 128;      // [64]
    float* sVb = sVs + 64;           // [64]

    int tid = threadIdx.x;
    int s = blockIdx.z, n = blockIdx.y;
    int p0 = blockIdx.x * TP1;
    int sn = s * NB + n;
    const float* xb = (s ? ir : rgb) + (size_t)n * CC * HWP;

    for (int idx = tid; idx < 128 * 64; idx += 256) {
        int o = idx >> 6, c = idx & 63;
        sW[o * 65 + c] = (o < 64) ? conv_w[o * 64 + c] : val_w[(o - 64) * 64 + c];
    }
    if (tid < 64) {
        float sc = val_g[tid] * rsqrtf(val_vv[tid] + EPSV);
        sVs[tid] = sc;
        sVb[tid] = val_b[tid] - val_m[tid] * sc;
    }
    for (int idx = tid; idx < 64 * 32; idx += 256) {
        int c = idx >> 5, i = idx & 31;
        float4 v = *(const float4*)(xb + (size_t)c * HWP + p0 + i * 4);
        *(float4*)(sX + c * 128 + i * 4) = v;
    }
    __syncthreads();

    int to = tid >> 4, tp = tid & 15;
    u64 acc[8][4];
#pragma unroll
    for (int i = 0; i < 8; i++)
#pragma unroll
        for (int j = 0; j < 4; j++) acc[i][j] = 0ull;

    const u64* sX2 = (const u64*)sX;   // float2 view, 64 per row
#pragma unroll 4
    for (int c = 0; c < 64; c++) {
        u64 xa0 = sX2[c * 64 + tp];
        u64 xa1 = sX2[c * 64 + tp + 16];
        u64 xa2 = sX2[c * 64 + tp + 32];
        u64 xa3 = sX2[c * 64 + tp + 48];
        const float* wc = sW + (to * 8) * 65 + c;
#pragma unroll
        for (int i = 0; i < 8; i++) {
            float w = wc[i * 65];
            u64 w2 = pack2(w, w);
            acc[i][0] = ffma2(w2, xa0, acc[i][0]);
            acc[i][1] = ffma2(w2, xa1, acc[i][1]);
            acc[i][2] = ffma2(w2, xa2, acc[i][2]);
            acc[i][3] = ffma2(w2, xa3, acc[i][3]);
        }
    }

    if (to < 8) {  // conv rows: spatial max (bias added in K2)
#pragma unroll
        for (int i = 0; i < 8; i++) {
            int o = to * 8 + i;
            float m = -3.4e38f;
#pragma unroll
            for (int j = 0; j < 4; j++) {
                float2 f = unpk(acc[i][j]);
                m = fmaxf(m, fmaxf(f.x, f.y));
            }
#pragma unroll
            for (int d = 8; d; d >>= 1) m = fmaxf(m, __shfl_xor_sync(0xffffffffu, m, d));
            if (tp == 0) atomicMax(&g_xcmax[sn * CC + o], fenc(m));
        }
    } else {       // val rows: bn + silu + store
#pragma unroll
        for (int i = 0; i < 8; i++) {
            int o = (to - 8) * 8 + i;
            float sc = sVs[o], sh = sVb[o];
            float2* dst = (float2*)(g_v + ((size_t)sn * CC + o) * HWP + p0);
#pragma unroll
            for (int j = 0; j < 4; j++) {
                float2 f = unpk(acc[i][j]);
                f.x = siluf(fmaf(f.x, sc, sh));
                f.y = siluf(fmaf(f.y, sc, sh));
                dst[tp + 16 * j] = f;
            }
        }
    }

    // key logits: one pixel per thread (tid < 128)
    if (tid < TP1) {
        float kscale = key_g[0] * rsqrtf(key_vv[0] + EPSV);
        float kshift = key_b[0] - key_m[0] * kscale;
        float a = 0.f;
#pragma unroll 8
        for (int c = 0; c < 64; c++) a = fmaf(key_w[c], sX[c * 128 + tid], a);
        float kl = siluf(fmaf(a, kscale, kshift));
        g_klog[(size_t)sn * HWP + p0 + tid] = kl;
        float km = kl;
#pragma unroll
        for (int d = 16; d; d >>= 1) km = fmaxf(km, __shfl_xor_sync(0xffffffffu, km, d));
        if ((tid & 31) == 0) atomicMax(&g_keymax[sn], fenc(km));
    }
    // per-channel spatial sums (rotated to avoid bank conflicts)
    if (tid < 64) {
        float a = 0.f;
        for (int j = 0; j < 128; j++) a += sX[tid * 128 + ((tid + j) & 127)];
        atomicAdd(&g_sumx[sn * CC + tid], a);
    }
}

// ---- K2: channel softmaxes for avg and max paths ----
__global__ void k2_avgmax(const float* __restrict__ conv_w, const float* __restrict__ conv_b) {
    int n = blockIdx.x, s = blockIdx.y, sn = s * NB + n;
    int t = threadIdx.x;  // 64 threads
    __shared__ float red[64];
    const float inv = 1.f / (float)HWP;
    float la = conv_b[t];
    for (int c = 0; c < 64; c++) la = fmaf(conv_w[t * 64 + c], g_sumx[sn * CC + c] * inv, la);
    float lm = fdec(g_xcmax[sn * CC + t]) + conv_b[t];

    red[t] = la; __syncthreads();
    for (int d = 32; d; d >>= 1) { if (t < d) red[t] = fmaxf(red[t], red[t + d]); __syncthreads(); }
    float M = red[0]; __syncthreads();
    float e = __expf(la - M);
    red[t] = e; __syncthreads();
    for (int d = 32; d; d >>= 1) { if (t < d) red[t] += red[t + d]; __syncthreads(); }
    g_avg[sn * CC + t] = e / red[0]; __syncthreads();

    red[t] = lm; __syncthreads();
    for (int d = 32; d; d >>= 1) { if (t < d) red[t] = fmaxf(red[t], red[t + d]); __syncthreads(); }
    M = red[0]; __syncthreads();
    e = __expf(lm - M);
    red[t] = e; __syncthreads();
    for (int d = 32; d; d >>= 1) { if (t < d) red[t] += red[t + d]; __syncthreads(); }
    g_mx[sn * CC + t] = e / red[0];
}

// ---- K3: fused streaming pass over g_v[other]:
//  Z + fea (softmax-weighted channel sums)  AND  avgm/maxm per-pixel channel mixes.
//  1024 blocks (vs 256 in R5) for occupancy; g_v is read here ONCE and never again.
__global__ void __launch_bounds__(256) k3_fea() {
    int me = blockIdx.z, n = blockIdx.y;
    int sn = me * NB + n, on = (1 - me) * NB + n;
    int tid = threadIdx.x, lane = tid & 31, wid = tid >> 5;
    int p0 = blockIdx.x * 1024;
    int px = p0 + wid * 128 + lane * 4;          // this lane's float4 pixel base

    __shared__ float savg[64], smx[64];
    __shared__ float sfea[64][9];                // [channel][warp], padded
    __shared__ float szred[8];

    if (tid < 64) { savg[tid] = g_avg[sn * CC + tid]; smx[tid] = g_mx[sn * CC + tid]; }

    float kmax = fdec(g_keymax[sn]);
    float4 kl4 = *(const float4*)(g_klog + (size_t)sn * HWP + px);
    float4 e4;
    e4.x = __expf(kl4.x - kmax); e4.y = __expf(kl4.y - kmax);
    e4.z = __expf(kl4.z - kmax); e4.w = __expf(kl4.w - kmax);
    float z = (e4.x + e4.y) + (e4.z + e4.w);
#pragma unroll
    for (int d = 16; d; d >>= 1) z += __shfl_xor_sync(0xffffffffu, z, d);
    if (lane == 0) szred[wid] = z;
    __syncthreads();                              // covers savg/smx + szred
    if (tid == 0) {
        float tt = 0.f;
#pragma unroll
        for (int i = 0; i < 8; i++) tt += szred[i];
        atomicAdd(&g_Z[sn], tt);
    }

    float4 am = {0.f, 0.f, 0.f, 0.f}, mm = {0.f, 0.f, 0.f, 0.f};
    const float* vb = g_v + (size_t)on * CC * HWP + px;
#pragma unroll 4
    for (int c = 0; c < 64; c++) {
        float4 v = *(const float4*)(vb + (size_t)c * HWP);
        float fe = fmaf(v.x, e4.x, fmaf(v.y, e4.y, fmaf(v.z, e4.z, v.w * e4.w)));
#pragma unroll
        for (int d = 16; d; d >>= 1) fe += __shfl_xor_sync(0xffffffffu, fe, d);
        if (lane == 0) sfea[c][wid] = fe;
        float a = savg[c], m = smx[c];
        am.x = fmaf(a, v.x, am.x); am.y = fmaf(a, v.y, am.y);
        am.z = fmaf(a, v.z, am.z); am.w = fmaf(a, v.w, am.w);
        mm.x = fmaf(m, v.x, mm.x); mm.y = fmaf(m, v.y, mm.y);
        mm.z = fmaf(m, v.z, mm.z); mm.w = fmaf(m, v.w, mm.w);
    }
    __syncthreads();
    if (tid < 64) {
        float s = 0.f;
#pragma unroll
        for (int w = 0; w < 8; w++) s += sfea[tid][w];
        atomicAdd(&g_feanum[sn * CC + tid], s);
    }
    *(float4*)(g_avgm + (size_t)sn * HWP + px) = am;
    *(float4*)(g_maxm + (size_t)sn * HWP + px) = mm;
}

// ---- K4: gate = sigmoid(LN(fea @ convb_w^T)) ----
__global__ void k4_gate(const float* __restrict__ convb_w,
                        const float* __restrict__ ln_g, const float* __restrict__ ln_b) {
    int n = blockIdx.x, me = blockIdx.y, sn = me * NB + n;
    int t = threadIdx.x;  // 64
    __shared__ float sf[64];
    __shared__ float red[64];
    float Z = g_Z[sn];
    sf[t] = g_feanum[sn * CC + t] / Z;
    __syncthreads();
    float v = 0.f;
    for (int c = 0; c < 64; c++) v = fmaf(convb_w[t * 64 + c], sf[c], v);
    red[t] = v; __syncthreads();
    for (int d = 32; d; d >>= 1) { if (t < d) red[t] += red[t + d]; __syncthreads(); }
    float mu = red[0] * (1.f / 64.f); __syncthreads();
    float dv = v - mu;
    red[t] = dv * dv; __syncthreads();
    for (int d = 32; d; d >>= 1) { if (t < d) red[t] += red[t + d]; __syncthreads(); }
    float var = red[0] * (1.f / 64.f);
    float nrm = fmaf(dv * rsqrtf(var + EPSV), ln_g[t], ln_b[t]);
    g_gate[sn * CC + t] = 1.f / (1.f + __expf(-nrm));
}

// ---- K5: half conv_block from precomputed avgm/maxm + gated residual output ----
//  No longer touches g_v (saves 268MB of HBM traffic vs R5).
__global__ void __launch_bounds__(256) k5_out(
    const float* __restrict__ rgb, const float* __restrict__ ir,
    const float* __restrict__ half_w, const float* __restrict__ half_g,
    const float* __restrict__ half_b, const float* __restrict__ half_m,
    const float* __restrict__ half_vv, float* __restrict__ out)
{
    int me = blockIdx.z, n = blockIdx.y, p0 = blockIdx.x * 1024;
    int sn = me * NB + n;
    int tid = threadIdx.x;
    __shared__ float sG[64];
    if (tid < 64) sG[tid] = g_gate[sn * CC + tid];
    __syncthreads();
    float h0 = half_w[0], h1 = half_w[1];
    float hsc = half_g[0] * rsqrtf(half_vv[0] + EPSV);
    float hsh = half_b[0] - half_m[0] * hsc;

    int px = p0 + tid * 4;
    float4 am = *(const float4*)(g_avgm + (size_t)sn * HWP + px);
    float4 mm = *(const float4*)(g_maxm + (size_t)sn * HWP + px);
    float4 h;
    h.x = siluf(fmaf(fmaf(h0, am.x, h1 * mm.x), hsc, hsh));
    h.y = siluf(fmaf(fmaf(h0, am.y, h1 * mm.y), hsc, hsh));
    h.z = siluf(fmaf(fmaf(h0, am.z, h1 * mm.z), hsc, hsh));
    h.w = siluf(fmaf(fmaf(h0, am.w, h1 * mm.w), hsc, hsh));

    size_t pq = (size_t)px >> 2;
    const float4* xme = (const float4*)((me ? ir : rgb) + (size_t)n * CC * HWP);
    float4* ob = (float4*)(out + (size_t)sn * CC * HWP);
#pragma unroll 8
    for (int c = 0; c < 64; c++) {
        float4 x4 = xme[(size_t)c * (HWP / 4) + pq];
        float g = sG[c];
        float4 o4;
        o4.x = fmaf(g, h.x, x4.x);
        o4.y = fmaf(g, h.y, x4.y);
        o4.z = fmaf(g, h.z, x4.z);
        o4.w = fmaf(g, h.w, x4.w);
        ob[(size_t)c * (HWP / 4) + pq] = o4;
    }
}

extern "C" void kernel_launch(void* const* d_in, const int* in_sizes, int n_in,
                              void* d_out, int out_size) {
    const float* rgb     = (const float*)d_in[0];
    const float* ir      = (const float*)d_in[1];
    const float* conv_w  = (const float*)d_in[2];
    const float* conv_b  = (const float*)d_in[3];
    const float* key_w   = (const float*)d_in[4];
    const float* key_g   = (const float*)d_in[5];
    const float* key_b   = (const float*)d_in[6];
    const float* key_m   = (const float*)d_in[7];
    const float* key_v   = (const float*)d_in[8];
    const float* val_w   = (const float*)d_in[9];
    const float* val_g   = (const float*)d_in[10];
    const float* val_b   = (const float*)d_in[11];
    const float* val_m   = (const float*)d_in[12];
    const float* val_v   = (const float*)d_in[13];
    const float* convb_w = (const float*)d_in[14];
    const float* half_w  = (const float*)d_in[15];
    const float* half_g  = (const float*)d_in[16];
    const float* half_b  = (const float*)d_in[17];
    const float* half_m  = (const float*)d_in[18];
    const float* half_v  = (const float*)d_in[19];
    const float* ln_g    = (const float*)d_in[20];
    const float* ln_b    = (const float*)d_in[21];
    float* out = (float*)d_out;

    const int smem1 = (128 * 65 + 64 * 128 + 128) * (int)sizeof(float);  // 66560
    cudaFuncSetAttribute(k1_main, cudaFuncAttributeMaxDynamicSharedMemorySize, smem1);

    k0_init<<<1, 1024>>>();
    k1_main<<<dim3(HWP / TP1, NB, SIDES), 256, smem1>>>(
        rgb, ir, conv_w, key_w, val_w, val_g, val_b, val_m, val_v,
        key_g, key_b, key_m, key_v);
    k2_avgmax<<<dim3(NB, SIDES), 64>>>(conv_w, conv_b);
    k3_fea<<<dim3(HWP / 1024, NB, SIDES), 256>>>();
    k4_gate<<<dim3(NB, SIDES), 64>>>(convb_w, ln_g, ln_b);
    k5_out<<<dim3(HWP / 1024, NB, SIDES), 256>>>(
        rgb, ir, half_w, half_g, half_b, half_m, half_v, out);
}

// round 8
// speedup vs baseline: 1.8148x; 1.6135x over previous
#include <cuda_runtime.h>

#define SIDES 2
#define NB 8
#define CC 64
#define HWP 65536
#define EPSV 1e-5f
#define TP1 128

typedef unsigned long long u64;
typedef unsigned int u32;

// ---- scratch (device globals; no runtime allocation) ----
__device__ float g_v[(size_t)SIDES * NB * CC * HWP];   // materialized val tensors (268MB)
__device__ float g_klog[(size_t)SIDES * NB * HWP];     // key logits (post-silu), 4MB
__device__ float g_avgm[(size_t)SIDES * NB * HWP];     // per-pixel avg-mix, 4MB
__device__ float g_maxm[(size_t)SIDES * NB * HWP];     // per-pixel max-mix, 4MB
__device__ float g_sumx[SIDES * NB * CC];
__device__ u32   g_xcmax[SIDES * NB * CC];             // encoded float max
__device__ u32   g_keymax[SIDES * NB];
__device__ float g_Z[SIDES * NB];
__device__ float g_feanum[SIDES * NB * CC];
__device__ float g_avg[SIDES * NB * CC];
__device__ float g_mx[SIDES * NB * CC];
__device__ float g_gate[SIDES * NB * CC];

// ---- helpers ----
__device__ __forceinline__ u32 fenc(float f) {
    u32 u = __float_as_uint(f);
    return (u & 0x80000000u) ? ~u : (u | 0x80000000u);
}
__device__ __forceinline__ float fdec(u32 u) {
    return __uint_as_float((u & 0x80000000u) ? (u & 0x7fffffffu) : ~u);
}
__device__ __forceinline__ float siluf(float x) { return x / (1.f + __expf(-x)); }
__device__ __forceinline__ float cvt_tf32(float x) {
    float r; asm("cvt.rna.tf32.f32 %0, %1;" : "=f"(r) : "f"(x)); return r;
}
// m16n8k8 tf32 MMA: D += A(16x8,row) * B(8x8,col)
__device__ __forceinline__ void mma_tf32(float* c, const u32* a, const u32* b) {
    asm("mma.sync.aligned.m16n8k8.row.col.f32.tf32.tf32.f32 "
        "{%0,%1,%2,%3},{%4,%5,%6,%7},{%8,%9},{%0,%1,%2,%3};"
        : "+f"(c[0]), "+f"(c[1]), "+f"(c[2]), "+f"(c[3])
        : "r"(a[0]), "r"(a[1]), "r"(a[2]), "r"(a[3]), "r"(b[0]), "r"(b[1]));
}

// ---- K0: reset accumulators (must re-run every launch for graph replay) ----
__global__ void k0_init() {
    int t = threadIdx.x;
    if (t < SIDES * NB * CC) { g_sumx[t] = 0.f; g_xcmax[t] = 0x007FFFFFu; g_feanum[t] = 0.f; }
    if (t < SIDES * NB) { g_keymax[t] = 0x007FFFFFu; g_Z[t] = 0.f; }
}

// ---- K1: tf32 tensor-core GEMM [conv_w;val_w](128x64) x X(64x128px) per CTA ----
//  smem: sW [128][68] (pad->A frags conflict-free), sX [64][136] (pad->B frags conflict-free)
#define SW_STR 68
#define SX_STR 136
__global__ void __launch_bounds__(256) k1_main(
    const float* __restrict__ rgb, const float* __restrict__ ir,
    const float* __restrict__ conv_w, const float* __restrict__ key_w,
    const float* __restrict__ val_w,
    const float* __restrict__ val_g, const float* __restrict__ val_b,
    const float* __restrict__ val_m, const float* __restrict__ val_vv,
    const float* __restrict__ key_g, const float* __restrict__ key_b,
    const float* __restrict__ key_m, const float* __restrict__ key_vv)
{
    extern __shared__ float sm[];
    float* sW   = sm;                        // [128][68]
    float* sX   = sm + 128 * SW_STR;         // [64][136]
    float* sVs  = sX + 64 * SX_STR;          // [64]
    float* sVb  = sVs + 64;                  // [64]
    float* ssum = sVb + 64;                  // [64]

    int tid = threadIdx.x;
    int s = blockIdx.z, n = blockIdx.y;
    int p0 = blockIdx.x * TP1;
    int sn = s * NB + n;
    const float* xb = (s ? ir : rgb) + (size_t)n * CC * HWP;

    // weights (tf32-rounded)
    for (int idx = tid; idx < 128 * 64; idx += 256) {
        int o = idx >> 6, c = idx & 63;
        float wv = (o < 64) ? conv_w[o * 64 + c] : val_w[(o - 64) * 64 + c];
        sW[o * SW_STR + c] = cvt_tf32(wv);
    }
    if (tid < 64) {
        float sc = val_g[tid] * rsqrtf(val_vv[tid] + EPSV);
        sVs[tid] = sc;
        sVb[tid] = val_b[tid] - val_m[tid] * sc;
    }
    // X tile (tf32-rounded) + per-channel partial sums (warp covers one channel per iter)
#pragma unroll
    for (int k = 0; k < 8; k++) {
        int idx = tid + 256 * k;
        int c = idx >> 5, i = idx & 31;
        float4 v = *(const float4*)(xb + (size_t)c * HWP + p0 + i * 4);
        v.x = cvt_tf32(v.x); v.y = cvt_tf32(v.y);
        v.z = cvt_tf32(v.z); v.w = cvt_tf32(v.w);
        float ps = (v.x + v.y) + (v.z + v.w);
#pragma unroll
        for (int d = 16; d; d >>= 1) ps += __shfl_xor_sync(0xffffffffu, ps, d);
        if ((tid & 31) == 0) ssum[c] = ps;
        *(float4*)(sX + c * SX_STR + i * 4) = v;
    }
    __syncthreads();

    if (tid < 64) atomicAdd(&g_sumx[sn * CC + tid], ssum[tid]);

    // ---- tensor-core GEMM: warp = 4 M-tiles x 4 N-tiles ----
    int w = tid >> 5, lane = tid & 31;
    int mg = w >> 2;              // 0: conv rows 0-63, 1: val rows 64-127
    int ng = w & 3;               // pixel group of 32
    int lr = lane >> 2, lc = lane & 3;

    float acc[4][4][4];
#pragma unroll
    for (int mt = 0; mt < 4; mt++)
#pragma unroll
        for (int nt = 0; nt < 4; nt++)
#pragma unroll
            for (int r = 0; r < 4; r++) acc[mt][nt][r] = 0.f;

#pragma unroll
    for (int ks = 0; ks < 8; ks++) {
        int k0 = ks * 8;
        u32 a[4][4];
#pragma unroll
        for (int mt = 0; mt < 4; mt++) {
            int mb = mg * 64 + mt * 16;
            a[mt][0] = __float_as_uint(sW[(mb + lr) * SW_STR + k0 + lc]);
            a[mt][1] = __float_as_uint(sW[(mb + lr + 8) * SW_STR + k0 + lc]);
            a[mt][2] = __float_as_uint(sW[(mb + lr) * SW_STR + k0 + lc + 4]);
            a[mt][3] = __float_as_uint(sW[(mb + lr + 8) * SW_STR + k0 + lc + 4]);
        }
        u32 b[4][2];
#pragma unroll
        for (int nt = 0; nt < 4; nt++) {
            int px = ng * 32 + nt * 8 + lr;
            b[nt][0] = __float_as_uint(sX[(k0 + lc) * SX_STR + px]);
            b[nt][1] = __float_as_uint(sX[(k0 + lc + 4) * SX_STR + px]);
        }
#pragma unroll
        for (int mt = 0; mt < 4; mt++)
#pragma unroll
            for (int nt = 0; nt < 4; nt++)
                mma_tf32(acc[mt][nt], a[mt], b[nt]);
    }

    // ---- epilogue ----
    if (mg == 0) {  // conv rows: spatial max (bias added in K2)
#pragma unroll
        for (int mt = 0; mt < 4; mt++) {
            float m1 = -3.4e38f, m2 = -3.4e38f;
#pragma unroll
            for (int nt = 0; nt < 4; nt++) {
                m1 = fmaxf(m1, fmaxf(acc[mt][nt][0], acc[mt][nt][1]));
                m2 = fmaxf(m2, fmaxf(acc[mt][nt][2], acc[mt][nt][3]));
            }
            m1 = fmaxf(m1, __shfl_xor_sync(0xffffffffu, m1, 1));
            m1 = fmaxf(m1, __shfl_xor_sync(0xffffffffu, m1, 2));
            m2 = fmaxf(m2, __shfl_xor_sync(0xffffffffu, m2, 1));
            m2 = fmaxf(m2, __shfl_xor_sync(0xffffffffu, m2, 2));
            if (lc == 0) {
                atomicMax(&g_xcmax[sn * CC + mt * 16 + lr], fenc(m1));
                atomicMax(&g_xcmax[sn * CC + mt * 16 + lr + 8], fenc(m2));
            }
        }
    } else {        // val rows: bn + silu + store
#pragma unroll
        for (int mt = 0; mt < 4; mt++) {
            int o1 = mt * 16 + lr, o2 = o1 + 8;
            float s1 = sVs[o1], h1 = sVb[o1];
            float s2 = sVs[o2], h2 = sVb[o2];
            float* r1 = g_v + ((size_t)sn * CC + o1) * HWP + p0 + ng * 32;
            float* r2 = g_v + ((size_t)sn * CC + o2) * HWP + p0 + ng * 32;
#pragma unroll
            for (int nt = 0; nt < 4; nt++) {
                int px = nt * 8 + 2 * lc;
                float2 f1, f2;
                f1.x = siluf(fmaf(acc[mt][nt][0], s1, h1));
                f1.y = siluf(fmaf(acc[mt][nt][1], s1, h1));
                f2.x = siluf(fmaf(acc[mt][nt][2], s2, h2));
                f2.y = siluf(fmaf(acc[mt][nt][3], s2, h2));
                *(float2*)(r1 + px) = f1;
                *(float2*)(r2 + px) = f2;
            }
        }
    }

    // key logits: one pixel per thread (tid < 128), from tf32-rounded sX
    if (tid < TP1) {
        float kscale = key_g[0] * rsqrtf(key_vv[0] + EPSV);
        float kshift = key_b[0] - key_m[0] * kscale;
        float a = 0.f;
#pragma unroll 8
        for (int c = 0; c < 64; c++) a = fmaf(key_w[c], sX[c * SX_STR + tid], a);
        float kl = siluf(fmaf(a, kscale, kshift));
        g_klog[(size_t)sn * HWP + p0 + tid] = kl;
        float km = kl;
#pragma unroll
        for (int d = 16; d; d >>= 1) km = fmaxf(km, __shfl_xor_sync(0xffffffffu, km, d));
        if ((tid & 31) == 0) atomicMax(&g_keymax[sn], fenc(km));
    }
}

// ---- K2: channel softmaxes for avg and max paths ----
__global__ void k2_avgmax(const float* __restrict__ conv_w, const float* __restrict__ conv_b) {
    int n = blockIdx.x, s = blockIdx.y, sn = s * NB + n;
    int t = threadIdx.x;  // 64 threads
    __shared__ float red[64];
    const float inv = 1.f / (float)HWP;
    float la = conv_b[t];
    for (int c = 0; c < 64; c++) la = fmaf(conv_w[t * 64 + c], g_sumx[sn * CC + c] * inv, la);
    float lm = fdec(g_xcmax[sn * CC + t]) + conv_b[t];

    red[t] = la; __syncthreads();
    for (int d = 32; d; d >>= 1) { if (t < d) red[t] = fmaxf(red[t], red[t + d]); __syncthreads(); }
    float M = red[0]; __syncthreads();
    float e = __expf(la - M);
    red[t] = e; __syncthreads();
    for (int d = 32; d; d >>= 1) { if (t < d) red[t] += red[t + d]; __syncthreads(); }
    g_avg[sn * CC + t] = e / red[0]; __syncthreads();

    red[t] = lm; __syncthreads();
    for (int d = 32; d; d >>= 1) { if (t < d) red[t] = fmaxf(red[t], red[t + d]); __syncthreads(); }
    M = red[0]; __syncthreads();
    e = __expf(lm - M);
    red[t] = e; __syncthreads();
    for (int d = 32; d; d >>= 1) { if (t < d) red[t] += red[t + d]; __syncthreads(); }
    g_mx[sn * CC + t] = e / red[0];
}

// ---- K3: fused streaming pass over g_v[other]: Z + fea AND avgm/maxm ----
__global__ void __launch_bounds__(256) k3_fea() {
    int me = blockIdx.z, n = blockIdx.y;
    int sn = me * NB + n, on = (1 - me) * NB + n;
    int tid = threadIdx.x, lane = tid & 31, wid = tid >> 5;
    int p0 = blockIdx.x * 1024;
    int px = p0 + wid * 128 + lane * 4;

    __shared__ float savg[64], smx[64];
    __shared__ float sfea[64][9];
    __shared__ float szred[8];

    if (tid < 64) { savg[tid] = g_avg[sn * CC + tid]; smx[tid] = g_mx[sn * CC + tid]; }

    float kmax = fdec(g_keymax[sn]);
    float4 kl4 = *(const float4*)(g_klog + (size_t)sn * HWP + px);
    float4 e4;
    e4.x = __expf(kl4.x - kmax); e4.y = __expf(kl4.y - kmax);
    e4.z = __expf(kl4.z - kmax); e4.w = __expf(kl4.w - kmax);
    float z = (e4.x + e4.y) + (e4.z + e4.w);
#pragma unroll
    for (int d = 16; d; d >>= 1) z += __shfl_xor_sync(0xffffffffu, z, d);
    if (lane == 0) szred[wid] = z;
    __syncthreads();
    if (tid == 0) {
        float tt = 0.f;
#pragma unroll
        for (int i = 0; i < 8; i++) tt += szred[i];
        atomicAdd(&g_Z[sn], tt);
    }

    float4 am = {0.f, 0.f, 0.f, 0.f}, mm = {0.f, 0.f, 0.f, 0.f};
    const float* vb = g_v + (size_t)on * CC * HWP + px;
#pragma unroll 4
    for (int c = 0; c < 64; c++) {
        float4 v = *(const float4*)(vb + (size_t)c * HWP);
        float fe = fmaf(v.x, e4.x, fmaf(v.y, e4.y, fmaf(v.z, e4.z, v.w * e4.w)));
#pragma unroll
        for (int d = 16; d; d >>= 1) fe += __shfl_xor_sync(0xffffffffu, fe, d);
        if (lane == 0) sfea[c][wid] = fe;
        float a = savg[c], m = smx[c];
        am.x = fmaf(a, v.x, am.x); am.y = fmaf(a, v.y, am.y);
        am.z = fmaf(a, v.z, am.z); am.w = fmaf(a, v.w, am.w);
        mm.x = fmaf(m, v.x, mm.x); mm.y = fmaf(m, v.y, mm.y);
        mm.z = fmaf(m, v.z, mm.z); mm.w = fmaf(m, v.w, mm.w);
    }
    __syncthreads();
    if (tid < 64) {
        float s = 0.f;
#pragma unroll
        for (int w = 0; w < 8; w++) s += sfea[tid][w];
        atomicAdd(&g_feanum[sn * CC + tid], s);
    }
    *(float4*)(g_avgm + (size_t)sn * HWP + px) = am;
    *(float4*)(g_maxm + (size_t)sn * HWP + px) = mm;
}

// ---- K4: gate = sigmoid(LN(fea @ convb_w^T)) ----
__global__ void k4_gate(const float* __restrict__ convb_w,
                        const float* __restrict__ ln_g, const float* __restrict__ ln_b) {
    int n = blockIdx.x, me = blockIdx.y, sn = me * NB + n;
    int t = threadIdx.x;  // 64
    __shared__ float sf[64];
    __shared__ float red[64];
    float Z = g_Z[sn];
    sf[t] = g_feanum[sn * CC + t] / Z;
    __syncthreads();
    float v = 0.f;
    for (int c = 0; c < 64; c++) v = fmaf(convb_w[t * 64 + c], sf[c], v);
    red[t] = v; __syncthreads();
    for (int d = 32; d; d >>= 1) { if (t < d) red[t] += red[t + d]; __syncthreads(); }
    float mu = red[0] * (1.f / 64.f); __syncthreads();
    float dv = v - mu;
    red[t] = dv * dv; __syncthreads();
    for (int d = 32; d; d >>= 1) { if (t < d) red[t] += red[t + d]; __syncthreads(); }
    float var = red[0] * (1.f / 64.f);
    float nrm = fmaf(dv * rsqrtf(var + EPSV), ln_g[t], ln_b[t]);
    g_gate[sn * CC + t] = 1.f / (1.f + __expf(-nrm));
}

// ---- K5: half conv_block from precomputed avgm/maxm + gated residual output ----
__global__ void __launch_bounds__(256) k5_out(
    const float* __restrict__ rgb, const float* __restrict__ ir,
    const float* __restrict__ half_w, const float* __restrict__ half_g,
    const float* __restrict__ half_b, const float* __restrict__ half_m,
    const float* __restrict__ half_vv, float* __restrict__ out)
{
    int me = blockIdx.z, n = blockIdx.y, p0 = blockIdx.x * 1024;
    int sn = me * NB + n;
    int tid = threadIdx.x;
    __shared__ float sG[64];
    if (tid < 64) sG[tid] = g_gate[sn * CC + tid];
    __syncthreads();
    float h0 = half_w[0], h1 = half_w[1];
    float hsc = half_g[0] * rsqrtf(half_vv[0] + EPSV);
    float hsh = half_b[0] - half_m[0] * hsc;

    int px = p0 + tid * 4;
    float4 am = *(const float4*)(g_avgm + (size_t)sn * HWP + px);
    float4 mm = *(const float4*)(g_maxm + (size_t)sn * HWP + px);
    float4 h;
    h.x = siluf(fmaf(fmaf(h0, am.x, h1 * mm.x), hsc, hsh));
    h.y = siluf(fmaf(fmaf(h0, am.y, h1 * mm.y), hsc, hsh));
    h.z = siluf(fmaf(fmaf(h0, am.z, h1 * mm.z), hsc, hsh));
    h.w = siluf(fmaf(fmaf(h0, am.w, h1 * mm.w), hsc, hsh));

    size_t pq = (size_t)px >> 2;
    const float4* xme = (const float4*)((me ? ir : rgb) + (size_t)n * CC * HWP);
    float4* ob = (float4*)(out + (size_t)sn * CC * HWP);
#pragma unroll 8
    for (int c = 0; c < 64; c++) {
        float4 x4 = xme[(size_t)c * (HWP / 4) + pq];
        float g = sG[c];
        float4 o4;
        o4.x = fmaf(g, h.x, x4.x);
        o4.y = fmaf(g, h.y, x4.y);
        o4.z = fmaf(g, h.z, x4.z);
        o4.w = fmaf(g, h.w, x4.w);
        ob[(size_t)c * (HWP / 4) + pq] = o4;
    }
}

extern "C" void kernel_launch(void* const* d_in, const int* in_sizes, int n_in,
                              void* d_out, int out_size) {
    const float* rgb     = (const float*)d_in[0];
    const float* ir      = (const float*)d_in[1];
    const float* conv_w  = (const float*)d_in[2];
    const float* conv_b  = (const float*)d_in[3];
    const float* key_w   = (const float*)d_in[4];
    const float* key_g   = (const float*)d_in[5];
    const float* key_b   = (const float*)d_in[6];
    const float* key_m   = (const float*)d_in[7];
    const float* key_v   = (const float*)d_in[8];
    const float* val_w   = (const float*)d_in[9];
    const float* val_g   = (const float*)d_in[10];
    const float* val_b   = (const float*)d_in[11];
    const float* val_m   = (const float*)d_in[12];
    const float* val_v   = (const float*)d_in[13];
    const float* convb_w = (const float*)d_in[14];
    const float* half_w  = (const float*)d_in[15];
    const float* half_g  = (const float*)d_in[16];
    const float* half_b  = (const float*)d_in[17];
    const float* half_m  = (const float*)d_in[18];
    const float* half_v  = (const float*)d_in[19];
    const float* ln_g    = (const float*)d_in[20];
    const float* ln_b    = (const float*)d_in[21];
    float* out = (float*)d_out;

    const int smem1 = (128 * SW_STR + 64 * SX_STR + 192) * (int)sizeof(float);  // 70400
    cudaFuncSetAttribute(k1_main, cudaFuncAttributeMaxDynamicSharedMemorySize, smem1);

    k0_init<<<1, 1024>>>();
    k1_main<<<dim3(HWP / TP1, NB, SIDES), 256, smem1>>>(
        rgb, ir, conv_w, key_w, val_w, val_g, val_b, val_m, val_v,
        key_g, key_b, key_m, key_v);
    k2_avgmax<<<dim3(NB, SIDES), 64>>>(conv_w, conv_b);
    k3_fea<<<dim3(HWP / 1024, NB, SIDES), 256>>>();
    k4_gate<<<dim3(NB, SIDES), 64>>>(convb_w, ln_g, ln_b);
    k5_out<<<dim3(HWP / 1024, NB, SIDES), 256>>>(
        rgb, ir, half_w, half_g, half_b, half_m, half_v, out);
}

// round 13
// speedup vs baseline: 2.1032x; 1.1589x over previous
#include <cuda_runtime.h>
#include <cuda_fp16.h>

#define SIDES 2
#define NB 8
#define CC 64
#define HWP 65536
#define EPSV 1e-5f
#define TP1 128

typedef unsigned long long u64;
typedef unsigned int u32;

// ---- scratch (device globals; no runtime allocation) ----
__device__ __half g_v[(size_t)SIDES * NB * CC * HWP];  // materialized val tensors (134MB, fp16)
__device__ float g_klog[(size_t)SIDES * NB * HWP];     // key logits (post-silu), 4MB
__device__ float g_avgm[(size_t)SIDES * NB * HWP];     // per-pixel avg-mix, 4MB
__device__ float g_maxm[(size_t)SIDES * NB * HWP];     // per-pixel max-mix, 4MB
__device__ float g_sumx[SIDES * NB * CC];
__device__ u32   g_xcmax[SIDES * NB * CC];             // encoded float max
__device__ u32   g_keymax[SIDES * NB];
__device__ float g_Z[SIDES * NB];
__device__ float g_feanum[SIDES * NB * CC];
__device__ float g_avg[SIDES * NB * CC];
__device__ float g_mx[SIDES * NB * CC];
__device__ float g_gate[SIDES * NB * CC];

// ---- helpers ----
__device__ __forceinline__ u32 fenc(float f) {
    u32 u = __float_as_uint(f);
    return (u & 0x80000000u) ? ~u : (u | 0x80000000u);
}
__device__ __forceinline__ float fdec(u32 u) {
    return __uint_as_float((u & 0x80000000u) ? (u & 0x7fffffffu) : ~u);
}
__device__ __forceinline__ float siluf(float x) { return x / (1.f + __expf(-x)); }
__device__ __forceinline__ u32 pack_h2(float a, float b) {
    __half2 h = __floats2half2_rn(a, b);
    return *(u32*)&h;
}
// m16n8k16 f16 MMA, fp32 accum: D += A(16x16,row) * B(16x8,col)
__device__ __forceinline__ void mma_f16(float* c, const u32* a, const u32* b) {
    asm("mma.sync.aligned.m16n8k16.row.col.f32.f16.f16.f32 "
        "{%0,%1,%2,%3},{%4,%5,%6,%7},{%8,%9},{%0,%1,%2,%3};"
        : "+f"(c[0]), "+f"(c[1]), "+f"(c[2]), "+f"(c[3])
        : "r"(a[0]), "r"(a[1]), "r"(a[2]), "r"(a[3]), "r"(b[0]), "r"(b[1]));
}

// ---- K0: reset accumulators (must re-run every launch for graph replay) ----
__global__ void k0_init() {
    int t = threadIdx.x;
    if (t < SIDES * NB * CC) { g_sumx[t] = 0.f; g_xcmax[t] = 0x007FFFFFu; g_feanum[t] = 0.f; }
    if (t < SIDES * NB) { g_keymax[t] = 0x007FFFFFu; g_Z[t] = 0.f; }
}

// ---- K1: fp16 tensor-core GEMM [conv_w;val_w](128x64) x X(64x128px) per CTA ----
//  sWh: [128 rows][36 half2]  (36%32==4 -> A-frag banks 4*lr+lc, conflict-free)
//  sXh: [32 kp][136 half2]    (136%32==8 -> B-frag banks 8*lc+lr, conflict-free)
//  half2 at (kp,px) packs {X[2kp][px], X[2kp+1][px]}  (K-pairs, matching f16 B frags)
#define SWH 36
#define SXH 136
__global__ void __launch_bounds__(256) k1_main(
    const float* __restrict__ rgb, const float* __restrict__ ir,
    const float* __restrict__ conv_w, const float* __restrict__ key_w,
    const float* __restrict__ val_w,
    const float* __restrict__ val_g, const float* __restrict__ val_b,
    const float* __restrict__ val_m, const float* __restrict__ val_vv,
    const float* __restrict__ key_g, const float* __restrict__ key_b,
    const float* __restrict__ key_m, const float* __restrict__ key_vv)
{
    extern __shared__ char smraw[];
    u32*   sWh  = (u32*)smraw;                       // 128*36 u32
    u32*   sXh  = sWh + 128 * SWH;                   // 32*136 u32
    float* sVs  = (float*)(sXh + 32 * SXH);          // [64]
    float* sVb  = sVs + 64;                          // [64]
    float* ssum = sVb + 64;                          // [64]

    int tid = threadIdx.x, lane = tid & 31;
    int s = blockIdx.z, n = blockIdx.y;
    int p0 = blockIdx.x * TP1;
    int sn = s * NB + n;
    const float* xb = (s ? ir : rgb) + (size_t)n * CC * HWP;

    // weights -> half2 K-pairs
    for (int idx = tid; idx < 128 * 32; idx += 256) {
        int o = idx >> 5, kp = idx & 31;
        float2 wv = (o < 64) ? *(const float2*)(conv_w + o * 64 + 2 * kp)
                             : *(const float2*)(val_w + (o - 64) * 64 + 2 * kp);
        sWh[o * SWH + kp] = pack_h2(wv.x, wv.y);
    }
    if (tid < 64) {
        float sc = val_g[tid] * rsqrtf(val_vv[tid] + EPSV);
        sVs[tid] = sc;
        sVb[tid] = val_b[tid] - val_m[tid] * sc;
    }
    // X tile: load channel pair, fp32 sums (pre-rounding), pack half2, uint4 store
#pragma unroll
    for (int it = 0; it < 4; it++) {
        int idx = tid + 256 * it;
        int kp = idx >> 5, i = idx & 31;
        const float* xp = xb + (size_t)(2 * kp) * HWP + p0 + i * 4;
        float4 lo = *(const float4*)xp;
        float4 hi = *(const float4*)(xp + HWP);
        float pl = (lo.x + lo.y) + (lo.z + lo.w);
        float ph = (hi.x + hi.y) + (hi.z + hi.w);
#pragma unroll
        for (int d = 16; d; d >>= 1) {
            pl += __shfl_xor_sync(0xffffffffu, pl, d);
            ph += __shfl_xor_sync(0xffffffffu, ph, d);
        }
        if (lane == 0) { ssum[2 * kp] = pl; ssum[2 * kp + 1] = ph; }
        uint4 st;
        st.x = pack_h2(lo.x, hi.x); st.y = pack_h2(lo.y, hi.y);
        st.z = pack_h2(lo.z, hi.z); st.w = pack_h2(lo.w, hi.w);
        *(uint4*)&sXh[kp * SXH + i * 4] = st;
    }
    __syncthreads();

    if (tid < 64) atomicAdd(&g_sumx[sn * CC + tid], ssum[tid]);

    // ---- tensor-core GEMM: warp = 4 M-tiles x 4 N-tiles, K=16 per MMA ----
    int w = tid >> 5;
    int mg = w >> 2;              // 0: conv rows 0-63, 1: val rows 64-127
    int ng = w & 3;               // pixel group of 32
    int lr = lane >> 2, lc = lane & 3;

    float acc[4][4][4];
#pragma unroll
    for (int mt = 0; mt < 4; mt++)
#pragma unroll
        for (int nt = 0; nt < 4; nt++)
#pragma unroll
            for (int r = 0; r < 4; r++) acc[mt][nt][r] = 0.f;

#pragma unroll
    for (int ks = 0; ks < 4; ks++) {
        int kp0 = ks * 8;
        u32 a[4][4];
#pragma unroll
        for (int mt = 0; mt < 4; mt++) {
            int mb = mg * 64 + mt * 16;
            a[mt][0] = sWh[(mb + lr) * SWH + kp0 + lc];
            a[mt][1] = sWh[(mb + lr + 8) * SWH + kp0 + lc];
            a[mt][2] = sWh[(mb + lr) * SWH + kp0 + lc + 4];
            a[mt][3] = sWh[(mb + lr + 8) * SWH + kp0 + lc + 4];
        }
        u32 b[4][2];
#pragma unroll
        for (int nt = 0; nt < 4; nt++) {
            int px = ng * 32 + nt * 8 + lr;
            b[nt][0] = sXh[(kp0 + lc) * SXH + px];
            b[nt][1] = sXh[(kp0 + lc + 4) * SXH + px];
        }
#pragma unroll
        for (int mt = 0; mt < 4; mt++)
#pragma unroll
            for (int nt = 0; nt < 4; nt++)
                mma_f16(acc[mt][nt], a[mt], b[nt]);
    }

    // ---- epilogue ----
    if (mg == 0) {  // conv rows: spatial max (bias added in K2)
#pragma unroll
        for (int mt = 0; mt < 4; mt++) {
            float m1 = -3.4e38f, m2 = -3.4e38f;
#pragma unroll
            for (int nt = 0; nt < 4; nt++) {
                m1 = fmaxf(m1, fmaxf(acc[mt][nt][0], acc[mt][nt][1]));
                m2 = fmaxf(m2, fmaxf(acc[mt][nt][2], acc[mt][nt][3]));
            }
            m1 = fmaxf(m1, __shfl_xor_sync(0xffffffffu, m1, 1));
            m1 = fmaxf(m1, __shfl_xor_sync(0xffffffffu, m1, 2));
            m2 = fmaxf(m2, __shfl_xor_sync(0xffffffffu, m2, 1));
            m2 = fmaxf(m2, __shfl_xor_sync(0xffffffffu, m2, 2));
            if (lc == 0) {
                atomicMax(&g_xcmax[sn * CC + mt * 16 + lr], fenc(m1));
                atomicMax(&g_xcmax[sn * CC + mt * 16 + lr + 8], fenc(m2));
            }
        }
    } else {        // val rows: bn + silu + fp16 store
#pragma unroll
        for (int mt = 0; mt < 4; mt++) {
            int o1 = mt * 16 + lr, o2 = o1 + 8;
            float s1 = sVs[o1], h1 = sVb[o1];
            float s2 = sVs[o2], h2 = sVb[o2];
            __half* r1 = g_v + ((size_t)sn * CC + o1) * HWP + p0 + ng * 32;
            __half* r2 = g_v + ((size_t)sn * CC + o2) * HWP + p0 + ng * 32;
#pragma unroll
            for (int nt = 0; nt < 4; nt++) {
                int px = nt * 8 + 2 * lc;
                u32 f1 = pack_h2(siluf(fmaf(acc[mt][nt][0], s1, h1)),
                                 siluf(fmaf(acc[mt][nt][1], s1, h1)));
                u32 f2 = pack_h2(siluf(fmaf(acc[mt][nt][2], s2, h2)),
                                 siluf(fmaf(acc[mt][nt][3], s2, h2)));
                *(u32*)(r1 + px) = f1;
                *(u32*)(r2 + px) = f2;
            }
        }
    }

    // key logits: one pixel per thread (tid < 128), from f16-rounded sX
    if (tid < TP1) {
        float kscale = key_g[0] * rsqrtf(key_vv[0] + EPSV);
        float kshift = key_b[0] - key_m[0] * kscale;
        float a = 0.f;
#pragma unroll 8
        for (int kp = 0; kp < 32; kp++) {
            u32 raw = sXh[kp * SXH + tid];
            float2 f = __half22float2(*(__half2*)&raw);
            a = fmaf(key_w[2 * kp], f.x, fmaf(key_w[2 * kp + 1], f.y, a));
        }
        float kl = siluf(fmaf(a, kscale, kshift));
        g_klog[(size_t)sn * HWP + p0 + tid] = kl;
        float km = kl;
#pragma unroll
        for (int d = 16; d; d >>= 1) km = fmaxf(km, __shfl_xor_sync(0xffffffffu, km, d));
        if ((tid & 31) == 0) atomicMax(&g_keymax[sn], fenc(km));
    }
}

// ---- K2: channel softmaxes for avg and max paths ----
__global__ void k2_avgmax(const float* __restrict__ conv_w, const float* __restrict__ conv_b) {
    int n = blockIdx.x, s = blockIdx.y, sn = s * NB + n;
    int t = threadIdx.x;  // 64 threads
    __shared__ float red[64];
    const float inv = 1.f / (float)HWP;
    float la = conv_b[t];
    for (int c = 0; c < 64; c++) la = fmaf(conv_w[t * 64 + c], g_sumx[sn * CC + c] * inv, la);
    float lm = fdec(g_xcmax[sn * CC + t]) + conv_b[t];

    red[t] = la; __syncthreads();
    for (int d = 32; d; d >>= 1) { if (t < d) red[t] = fmaxf(red[t], red[t + d]); __syncthreads(); }
    float M = red[0]; __syncthreads();
    float e = __expf(la - M);
    red[t] = e; __syncthreads();
    for (int d = 32; d; d >>= 1) { if (t < d) red[t] += red[t + d]; __syncthreads(); }
    g_avg[sn * CC + t] = e / red[0]; __syncthreads();

    red[t] = lm; __syncthreads();
    for (int d = 32; d; d >>= 1) { if (t < d) red[t] = fmaxf(red[t], red[t + d]); __syncthreads(); }
    M = red[0]; __syncthreads();
    e = __expf(lm - M);
    red[t] = e; __syncthreads();
    for (int d = 32; d; d >>= 1) { if (t < d) red[t] += red[t + d]; __syncthreads(); }
    g_mx[sn * CC + t] = e / red[0];
}

// ---- K3: fused streaming pass over fp16 g_v[other]: Z + fea AND avgm/maxm ----
__global__ void __launch_bounds__(256) k3_fea() {
    int me = blockIdx.z, n = blockIdx.y;
    int sn = me * NB + n, on = (1 - me) * NB + n;
    int tid = threadIdx.x, lane = tid & 31, wid = tid >> 5;
    int p0 = blockIdx.x * 1024;
    int px = p0 + wid * 128 + lane * 4;

    __shared__ float savg[64], smx[64];
    __shared__ float sfea[64][9];
    __shared__ float szred[8];

    if (tid < 64) { savg[tid] = g_avg[sn * CC + tid]; smx[tid] = g_mx[sn * CC + tid]; }

    float kmax = fdec(g_keymax[sn]);
    float4 kl4 = *(const float4*)(g_klog + (size_t)sn * HWP + px);
    float4 e4;
    e4.x = __expf(kl4.x - kmax); e4.y = __expf(kl4.y - kmax);
    e4.z = __expf(kl4.z - kmax); e4.w = __expf(kl4.w - kmax);
    float z = (e4.x + e4.y) + (e4.z + e4.w);
#pragma unroll
    for (int d = 16; d; d >>= 1) z += __shfl_xor_sync(0xffffffffu, z, d);
    if (lane == 0) szred[wid] = z;
    __syncthreads();
    if (tid == 0) {
        float tt = 0.f;
#pragma unroll
        for (int i = 0; i < 8; i++) tt += szred[i];
        atomicAdd(&g_Z[sn], tt);
    }

    float4 am = {0.f, 0.f, 0.f, 0.f}, mm = {0.f, 0.f, 0.f, 0.f};
    const __half* vb = g_v + (size_t)on * CC * HWP + px;
#pragma unroll 4
    for (int c = 0; c < 64; c++) {
        uint2 raw = *(const uint2*)(vb + (size_t)c * HWP);
        float2 f01 = __half22float2(*(__half2*)&raw.x);
        float2 f23 = __half22float2(*(__half2*)&raw.y);
        float fe = fmaf(f01.x, e4.x, fmaf(f01.y, e4.y, fmaf(f23.x, e4.z, f23.y * e4.w)));
#pragma unroll
        for (int d = 16; d; d >>= 1) fe += __shfl_xor_sync(0xffffffffu, fe, d);
        if (lane == 0) sfea[c][wid] = fe;
        float a = savg[c], m = smx[c];
        am.x = fmaf(a, f01.x, am.x); am.y = fmaf(a, f01.y, am.y);
        am.z = fmaf(a, f23.x, am.z); am.w = fmaf(a, f23.y, am.w);
        mm.x = fmaf(m, f01.x, mm.x); mm.y = fmaf(m, f01.y, mm.y);
        mm.z = fmaf(m, f23.x, mm.z); mm.w = fmaf(m, f23.y, mm.w);
    }
    __syncthreads();
    if (tid < 64) {
        float s = 0.f;
#pragma unroll
        for (int w = 0; w < 8; w++) s += sfea[tid][w];
        atomicAdd(&g_feanum[sn * CC + tid], s);
    }
    *(float4*)(g_avgm + (size_t)sn * HWP + px) = am;
    *(float4*)(g_maxm + (size_t)sn * HWP + px) = mm;
}

// ---- K4: gate = sigmoid(LN(fea @ convb_w^T)) ----
__global__ void k4_gate(const float* __restrict__ convb_w,
                        const float* __restrict__ ln_g, const float* __restrict__ ln_b) {
    int n = blockIdx.x, me = blockIdx.y, sn = me * NB + n;
    int t = threadIdx.x;  // 64
    __shared__ float sf[64];
    __shared__ float red[64];
    float Z = g_Z[sn];
    sf[t] = g_feanum[sn * CC + t] / Z;
    __syncthreads();
    float v = 0.f;
    for (int c = 0; c < 64; c++) v = fmaf(convb_w[t * 64 + c], sf[c], v);
    red[t] = v; __syncthreads();
    for (int d = 32; d; d >>= 1) { if (t < d) red[t] += red[t + d]; __syncthreads(); }
    float mu = red[0] * (1.f / 64.f); __syncthreads();
    float dv = v - mu;
    red[t] = dv * dv; __syncthreads();
    for (int d = 32; d; d >>= 1) { if (t < d) red[t] += red[t + d]; __syncthreads(); }
    float var = red[0] * (1.f / 64.f);
    float nrm = fmaf(dv * rsqrtf(var + EPSV), ln_g[t], ln_b[t]);
    g_gate[sn * CC + t] = 1.f / (1.f + __expf(-nrm));
}

// ---- K5: half conv_block from precomputed avgm/maxm + gated residual output ----
__global__ void __launch_bounds__(256) k5_out(
    const float* __restrict__ rgb, const float* __restrict__ ir,
    const float* __restrict__ half_w, const float* __restrict__ half_g,
    const float* __restrict__ half_b, const float* __restrict__ half_m,
    const float* __restrict__ half_vv, float* __restrict__ out)
{
    int me = blockIdx.z, n = blockIdx.y, p0 = blockIdx.x * 1024;
    int sn = me * NB + n;
    int tid = threadIdx.x;
    __shared__ float sG[64];
    if (tid < 64) sG[tid] = g_gate[sn * CC + tid];
    __syncthreads();
    float h0 = half_w[0], h1 = half_w[1];
    float hsc = half_g[0] * rsqrtf(half_vv[0] + EPSV);
    float hsh = half_b[0] - half_m[0] * hsc;

    int px = p0 + tid * 4;
    float4 am = *(const float4*)(g_avgm + (size_t)sn * HWP + px);
    float4 mm = *(const float4*)(g_maxm + (size_t)sn * HWP + px);
    float4 h;
    h.x = siluf(fmaf(fmaf(h0, am.x, h1 * mm.x), hsc, hsh));
    h.y = siluf(fmaf(fmaf(h0, am.y, h1 * mm.y), hsc, hsh));
    h.z = siluf(fmaf(fmaf(h0, am.z, h1 * mm.z), hsc, hsh));
    h.w = siluf(fmaf(fmaf(h0, am.w, h1 * mm.w), hsc, hsh));

    size_t pq = (size_t)px >> 2;
    const float4* xme = (const float4*)((me ? ir : rgb) + (size_t)n * CC * HWP);
    float4* ob = (float4*)(out + (size_t)sn * CC * HWP);
#pragma unroll 8
    for (int c = 0; c < 64; c++) {
        float4 x4 = xme[(size_t)c * (HWP / 4) + pq];
        float g = sG[c];
        float4 o4;
        o4.x = fmaf(g, h.x, x4.x);
        o4.y = fmaf(g, h.y, x4.y);
        o4.z = fmaf(g, h.z, x4.z);
        o4.w = fmaf(g, h.w, x4.w);
        ob[(size_t)c * (HWP / 4) + pq] = o4;
    }
}

extern "C" void kernel_launch(void* const* d_in, const int* in_sizes, int n_in,
                              void* d_out, int out_size) {
    const float* rgb     = (const float*)d_in[0];
    const float* ir      = (const float*)d_in[1];
    const float* conv_w  = (const float*)d_in[2];
    const float* conv_b  = (const float*)d_in[3];
    const float* key_w   = (const float*)d_in[4];
    const float* key_g   = (const float*)d_in[5];
    const float* key_b   = (const float*)d_in[6];
    const float* key_m   = (const float*)d_in[7];
    const float* key_v   = (const float*)d_in[8];
    const float* val_w   = (const float*)d_in[9];
    const float* val_g   = (const float*)d_in[10];
    const float* val_b   = (const float*)d_in[11];
    const float* val_m   = (const float*)d_in[12];
    const float* val_v   = (const float*)d_in[13];
    const float* convb_w = (const float*)d_in[14];
    const float* half_w  = (const float*)d_in[15];
    const float* half_g  = (const float*)d_in[16];
    const float* half_b  = (const float*)d_in[17];
    const float* half_m  = (const float*)d_in[18];
    const float* half_v  = (const float*)d_in[19];
    const float* ln_g    = (const float*)d_in[20];
    const float* ln_b    = (const float*)d_in[21];
    float* out = (float*)d_out;

    const int smem1 = (128 * SWH + 32 * SXH) * 4 + 192 * 4;  // ~36.6KB
    cudaFuncSetAttribute(k1_main, cudaFuncAttributeMaxDynamicSharedMemorySize, smem1);

    k0_init<<<1, 1024>>>();
    k1_main<<<dim3(HWP / TP1, NB, SIDES), 256, smem1>>>(
        rgb, ir, conv_w, key_w, val_w, val_g, val_b, val_m, val_v,
        key_g, key_b, key_m, key_v);
    k2_avgmax<<<dim3(NB, SIDES), 64>>>(conv_w, conv_b);
    k3_fea<<<dim3(HWP / 1024, NB, SIDES), 256>>>();
    k4_gate<<<dim3(NB, SIDES), 64>>>(convb_w, ln_g, ln_b);
    k5_out<<<dim3(HWP / 1024, NB, SIDES), 256>>>(
        rgb, ir, half_w, half_g, half_b, half_m, half_v, out);
}

// round 14
// speedup vs baseline: 2.1750x; 1.0342x over previous
#include <cuda_runtime.h>
#include <cuda_fp16.h>

#define SIDES 2
#define NB 8
#define CC 64
#define HWP 65536
#define EPSV 1e-5f
#define TP1 256

typedef unsigned long long u64;
typedef unsigned int u32;

// ---- scratch (device globals; no runtime allocation) ----
__device__ __half g_v[(size_t)SIDES * NB * CC * HWP];  // materialized val tensors (134MB, fp16)
__device__ float g_klog[(size_t)SIDES * NB * HWP];     // key logits (post-silu), 4MB
__device__ float g_avgm[(size_t)SIDES * NB * HWP];     // per-pixel avg-mix, 4MB
__device__ float g_maxm[(size_t)SIDES * NB * HWP];     // per-pixel max-mix, 4MB
__device__ float g_sumx[SIDES * NB * CC];
__device__ u32   g_xcmax[SIDES * NB * CC];             // encoded float max
__device__ u32   g_keymax[SIDES * NB];
__device__ float g_Z[SIDES * NB];
__device__ float g_feanum[SIDES * NB * CC];
__device__ float g_avg[SIDES * NB * CC];
__device__ float g_mx[SIDES * NB * CC];
__device__ float g_gate[SIDES * NB * CC];

// ---- helpers ----
__device__ __forceinline__ u32 fenc(float f) {
    u32 u = __float_as_uint(f);
    return (u & 0x80000000u) ? ~u : (u | 0x80000000u);
}
__device__ __forceinline__ float fdec(u32 u) {
    return __uint_as_float((u & 0x80000000u) ? (u & 0x7fffffffu) : ~u);
}
__device__ __forceinline__ float siluf(float x) { return x / (1.f + __expf(-x)); }
__device__ __forceinline__ u32 pack_h2(float a, float b) {
    __half2 h = __floats2half2_rn(a, b);
    return *(u32*)&h;
}
// m16n8k16 f16 MMA, fp32 accum: D += A(16x16,row) * B(16x8,col)
__device__ __forceinline__ void mma_f16(float* c, const u32* a, const u32* b) {
    asm("mma.sync.aligned.m16n8k16.row.col.f32.f16.f16.f32 "
        "{%0,%1,%2,%3},{%4,%5,%6,%7},{%8,%9},{%0,%1,%2,%3};"
        : "+f"(c[0]), "+f"(c[1]), "+f"(c[2]), "+f"(c[3])
        : "r"(a[0]), "r"(a[1]), "r"(a[2]), "r"(a[3]), "r"(b[0]), "r"(b[1]));
}

// ---- K0: reset accumulators (must re-run every launch for graph replay) ----
__global__ void k0_init() {
    int t = threadIdx.x;
    if (t < SIDES * NB * CC) { g_sumx[t] = 0.f; g_xcmax[t] = 0x007FFFFFu; g_feanum[t] = 0.f; }
    if (t < SIDES * NB) { g_keymax[t] = 0x007FFFFFu; g_Z[t] = 0.f; }
}

// ---- K1: fp16 tensor-core GEMM [conv_w;val_w](128x64) x X(64x256px), 512 threads ----
//  sWh: [128 rows][36 half2]   (36%32==4  -> A-frag banks conflict-free)
//  sXh: [32 kp][264 half2]     (264%32==8 -> B-frag banks conflict-free)
#define SWH 36
#define SXH 264
__global__ void __launch_bounds__(512) k1_main(
    const float* __restrict__ rgb, const float* __restrict__ ir,
    const float* __restrict__ conv_w, const float* __restrict__ key_w,
    const float* __restrict__ val_w,
    const float* __restrict__ val_g, const float* __restrict__ val_b,
    const float* __restrict__ val_m, const float* __restrict__ val_vv,
    const float* __restrict__ key_g, const float* __restrict__ key_b,
    const float* __restrict__ key_m, const float* __restrict__ key_vv)
{
    extern __shared__ char smraw[];
    u32*   sWh  = (u32*)smraw;                       // 128*36 u32
    u32*   sXh  = sWh + 128 * SWH;                   // 32*264 u32
    float* sVs  = (float*)(sXh + 32 * SXH);          // [64]
    float* sVb  = sVs + 64;                          // [64]
    float* ssum = sVb + 64;                          // [64]

    int tid = threadIdx.x, lane = tid & 31, w = tid >> 5;  // 16 warps
    int s = blockIdx.z, n = blockIdx.y;
    int p0 = blockIdx.x * TP1;
    int sn = s * NB + n;
    const float* xb = (s ? ir : rgb) + (size_t)n * CC * HWP;

    // weights -> half2 K-pairs (8 per thread)
    for (int idx = tid; idx < 128 * 32; idx += 512) {
        int o = idx >> 5, kp = idx & 31;
        float2 wv = (o < 64) ? *(const float2*)(conv_w + o * 64 + 2 * kp)
                             : *(const float2*)(val_w + (o - 64) * 64 + 2 * kp);
        sWh[o * SWH + kp] = pack_h2(wv.x, wv.y);
    }
    if (tid < 64) {
        float sc = val_g[tid] * rsqrtf(val_vv[tid] + EPSV);
        sVs[tid] = sc;
        sVb[tid] = val_b[tid] - val_m[tid] * sc;
    }
    // X tile: each warp owns channel-pair rows kp = w, w+16.  256 px per row.
#pragma unroll
    for (int it = 0; it < 2; it++) {
        int kp = w + 16 * it;
        const float* xp = xb + (size_t)(2 * kp) * HWP + p0 + 4 * lane;
        float4 lo1 = *(const float4*)xp;
        float4 lo2 = *(const float4*)(xp + 128);
        float4 hi1 = *(const float4*)(xp + HWP);
        float4 hi2 = *(const float4*)(xp + HWP + 128);
        float pl = ((lo1.x + lo1.y) + (lo1.z + lo1.w)) + ((lo2.x + lo2.y) + (lo2.z + lo2.w));
        float ph = ((hi1.x + hi1.y) + (hi1.z + hi1.w)) + ((hi2.x + hi2.y) + (hi2.z + hi2.w));
#pragma unroll
        for (int d = 16; d; d >>= 1) {
            pl += __shfl_xor_sync(0xffffffffu, pl, d);
            ph += __shfl_xor_sync(0xffffffffu, ph, d);
        }
        if (lane == 0) { ssum[2 * kp] = pl; ssum[2 * kp + 1] = ph; }
        uint4 a, b;
        a.x = pack_h2(lo1.x, hi1.x); a.y = pack_h2(lo1.y, hi1.y);
        a.z = pack_h2(lo1.z, hi1.z); a.w = pack_h2(lo1.w, hi1.w);
        b.x = pack_h2(lo2.x, hi2.x); b.y = pack_h2(lo2.y, hi2.y);
        b.z = pack_h2(lo2.z, hi2.z); b.w = pack_h2(lo2.w, hi2.w);
        *(uint4*)&sXh[kp * SXH + 4 * lane] = a;
        *(uint4*)&sXh[kp * SXH + 128 + 4 * lane] = b;
    }
    __syncthreads();

    if (tid < 64) atomicAdd(&g_sumx[sn * CC + tid], ssum[tid]);

    // ---- tensor-core GEMM: 16 warps = 2 M-groups x 8 N-groups; 4x4 tiles each ----
    int mg = w >> 3;              // 0: conv rows 0-63, 1: val rows 64-127
    int ng = w & 7;               // pixel group of 32
    int lr = lane >> 2, lc = lane & 3;

    float acc[4][4][4];
#pragma unroll
    for (int mt = 0; mt < 4; mt++)
#pragma unroll
        for (int nt = 0; nt < 4; nt++)
#pragma unroll
            for (int r = 0; r < 4; r++) acc[mt][nt][r] = 0.f;

#pragma unroll
    for (int ks = 0; ks < 4; ks++) {
        int kp0 = ks * 8;
        u32 a[4][4];
#pragma unroll
        for (int mt = 0; mt < 4; mt++) {
            int mb = mg * 64 + mt * 16;
            a[mt][0] = sWh[(mb + lr) * SWH + kp0 + lc];
            a[mt][1] = sWh[(mb + lr + 8) * SWH + kp0 + lc];
            a[mt][2] = sWh[(mb + lr) * SWH + kp0 + lc + 4];
            a[mt][3] = sWh[(mb + lr + 8) * SWH + kp0 + lc + 4];
        }
        u32 b[4][2];
#pragma unroll
        for (int nt = 0; nt < 4; nt++) {
            int px = ng * 32 + nt * 8 + lr;
            b[nt][0] = sXh[(kp0 + lc) * SXH + px];
            b[nt][1] = sXh[(kp0 + lc + 4) * SXH + px];
        }
#pragma unroll
        for (int mt = 0; mt < 4; mt++)
#pragma unroll
            for (int nt = 0; nt < 4; nt++)
                mma_f16(acc[mt][nt], a[mt], b[nt]);
    }

    // ---- epilogue ----
    if (mg == 0) {  // conv rows: spatial max (bias added in K2)
#pragma unroll
        for (int mt = 0; mt < 4; mt++) {
            float m1 = -3.4e38f, m2 = -3.4e38f;
#pragma unroll
            for (int nt = 0; nt < 4; nt++) {
                m1 = fmaxf(m1, fmaxf(acc[mt][nt][0], acc[mt][nt][1]));
                m2 = fmaxf(m2, fmaxf(acc[mt][nt][2], acc[mt][nt][3]));
            }
            m1 = fmaxf(m1, __shfl_xor_sync(0xffffffffu, m1, 1));
            m1 = fmaxf(m1, __shfl_xor_sync(0xffffffffu, m1, 2));
            m2 = fmaxf(m2, __shfl_xor_sync(0xffffffffu, m2, 1));
            m2 = fmaxf(m2, __shfl_xor_sync(0xffffffffu, m2, 2));
            if (lc == 0) {
                atomicMax(&g_xcmax[sn * CC + mt * 16 + lr], fenc(m1));
                atomicMax(&g_xcmax[sn * CC + mt * 16 + lr + 8], fenc(m2));
            }
        }
    } else {        // val rows: bn + silu + fp16 store
#pragma unroll
        for (int mt = 0; mt < 4; mt++) {
            int o1 = mt * 16 + lr, o2 = o1 + 8;
            float s1 = sVs[o1], h1 = sVb[o1];
            float s2 = sVs[o2], h2 = sVb[o2];
            __half* r1 = g_v + ((size_t)sn * CC + o1) * HWP + p0 + ng * 32;
            __half* r2 = g_v + ((size_t)sn * CC + o2) * HWP + p0 + ng * 32;
#pragma unroll
            for (int nt = 0; nt < 4; nt++) {
                int px = nt * 8 + 2 * lc;
                u32 f1 = pack_h2(siluf(fmaf(acc[mt][nt][0], s1, h1)),
                                 siluf(fmaf(acc[mt][nt][1], s1, h1)));
                u32 f2 = pack_h2(siluf(fmaf(acc[mt][nt][2], s2, h2)),
                                 siluf(fmaf(acc[mt][nt][3], s2, h2)));
                *(u32*)(r1 + px) = f1;
                *(u32*)(r2 + px) = f2;
            }
        }
    }

    // key logits: one pixel per thread (tid < 256)
    if (tid < TP1) {
        float kscale = key_g[0] * rsqrtf(key_vv[0] + EPSV);
        float kshift = key_b[0] - key_m[0] * kscale;
        float a = 0.f;
#pragma unroll 8
        for (int kp = 0; kp < 32; kp++) {
            u32 raw = sXh[kp * SXH + tid];
            float2 f = __half22float2(*(__half2*)&raw);
            a = fmaf(key_w[2 * kp], f.x, fmaf(key_w[2 * kp + 1], f.y, a));
        }
        float kl = siluf(fmaf(a, kscale, kshift));
        g_klog[(size_t)sn * HWP + p0 + tid] = kl;
        float km = kl;
#pragma unroll
        for (int d = 16; d; d >>= 1) km = fmaxf(km, __shfl_xor_sync(0xffffffffu, km, d));
        if ((tid & 31) == 0) atomicMax(&g_keymax[sn], fenc(km));
    }
}

// ---- K2: channel softmaxes for avg and max paths ----
__global__ void k2_avgmax(const float* __restrict__ conv_w, const float* __restrict__ conv_b) {
    int n = blockIdx.x, s = blockIdx.y, sn = s * NB + n;
    int t = threadIdx.x;  // 64 threads
    __shared__ float red[64];
    const float inv = 1.f / (float)HWP;
    float la = conv_b[t];
    for (int c = 0; c < 64; c++) la = fmaf(conv_w[t * 64 + c], g_sumx[sn * CC + c] * inv, la);
    float lm = fdec(g_xcmax[sn * CC + t]) + conv_b[t];

    red[t] = la; __syncthreads();
    for (int d = 32; d; d >>= 1) { if (t < d) red[t] = fmaxf(red[t], red[t + d]); __syncthreads(); }
    float M = red[0]; __syncthreads();
    float e = __expf(la - M);
    red[t] = e; __syncthreads();
    for (int d = 32; d; d >>= 1) { if (t < d) red[t] += red[t + d]; __syncthreads(); }
    g_avg[sn * CC + t] = e / red[0]; __syncthreads();

    red[t] = lm; __syncthreads();
    for (int d = 32; d; d >>= 1) { if (t < d) red[t] = fmaxf(red[t], red[t + d]); __syncthreads(); }
    M = red[0]; __syncthreads();
    e = __expf(lm - M);
    red[t] = e; __syncthreads();
    for (int d = 32; d; d >>= 1) { if (t < d) red[t] += red[t + d]; __syncthreads(); }
    g_mx[sn * CC + t] = e / red[0];
}

// ---- K3: fused streaming over fp16 g_v[other], 8 px/thread: Z + fea + avgm/maxm ----
__global__ void __launch_bounds__(128) k3_fea() {
    int me = blockIdx.z, n = blockIdx.y;
    int sn = me * NB + n, on = (1 - me) * NB + n;
    int tid = threadIdx.x, lane = tid & 31, wid = tid >> 5;  // 4 warps
    int p0 = blockIdx.x * 1024;
    int px = p0 + wid * 256 + lane * 8;

    __shared__ float savg[64], smx[64];
    __shared__ float sfea[64][5];                // [channel][warp], padded
    __shared__ float szred[4];

    if (tid < 64) { savg[tid] = g_avg[sn * CC + tid]; smx[tid] = g_mx[sn * CC + tid]; }

    float kmax = fdec(g_keymax[sn]);
    const float* klp = g_klog + (size_t)sn * HWP + px;
    float4 ka = *(const float4*)klp;
    float4 kb = *(const float4*)(klp + 4);
    float4 ea, eb;
    ea.x = __expf(ka.x - kmax); ea.y = __expf(ka.y - kmax);
    ea.z = __expf(ka.z - kmax); ea.w = __expf(ka.w - kmax);
    eb.x = __expf(kb.x - kmax); eb.y = __expf(kb.y - kmax);
    eb.z = __expf(kb.z - kmax); eb.w = __expf(kb.w - kmax);
    float z = ((ea.x + ea.y) + (ea.z + ea.w)) + ((eb.x + eb.y) + (eb.z + eb.w));
#pragma unroll
    for (int d = 16; d; d >>= 1) z += __shfl_xor_sync(0xffffffffu, z, d);
    if (lane == 0) szred[wid] = z;
    __syncthreads();
    if (tid == 0) {
        float tt = (szred[0] + szred[1]) + (szred[2] + szred[3]);
        atomicAdd(&g_Z[sn], tt);
    }

    float4 am1 = {0,0,0,0}, am2 = {0,0,0,0}, mm1 = {0,0,0,0}, mm2 = {0,0,0,0};
    const __half* vb = g_v + (size_t)on * CC * HWP + px;
#pragma unroll 4
    for (int c = 0; c < 64; c++) {
        uint4 raw = *(const uint4*)(vb + (size_t)c * HWP);
        float2 f01 = __half22float2(*(__half2*)&raw.x);
        float2 f23 = __half22float2(*(__half2*)&raw.y);
        float2 f45 = __half22float2(*(__half2*)&raw.z);
        float2 f67 = __half22float2(*(__half2*)&raw.w);
        float fe = fmaf(f01.x, ea.x, fmaf(f01.y, ea.y, fmaf(f23.x, ea.z, f23.y * ea.w)))
                 + fmaf(f45.x, eb.x, fmaf(f45.y, eb.y, fmaf(f67.x, eb.z, f67.y * eb.w)));
#pragma unroll
        for (int d = 16; d; d >>= 1) fe += __shfl_xor_sync(0xffffffffu, fe, d);
        if (lane == 0) sfea[c][wid] = fe;
        float a = savg[c], m = smx[c];
        am1.x = fmaf(a, f01.x, am1.x); am1.y = fmaf(a, f01.y, am1.y);
        am1.z = fmaf(a, f23.x, am1.z); am1.w = fmaf(a, f23.y, am1.w);
        am2.x = fmaf(a, f45.x, am2.x); am2.y = fmaf(a, f45.y, am2.y);
        am2.z = fmaf(a, f67.x, am2.z); am2.w = fmaf(a, f67.y, am2.w);
        mm1.x = fmaf(m, f01.x, mm1.x); mm1.y = fmaf(m, f01.y, mm1.y);
        mm1.z = fmaf(m, f23.x, mm1.z); mm1.w = fmaf(m, f23.y, mm1.w);
        mm2.x = fmaf(m, f45.x, mm2.x); mm2.y = fmaf(m, f45.y, mm2.y);
        mm2.z = fmaf(m, f67.x, mm2.z); mm2.w = fmaf(m, f67.y, mm2.w);
    }
    __syncthreads();
    if (tid < 64) {
        float s = (sfea[tid][0] + sfea[tid][1]) + (sfea[tid][2] + sfea[tid][3]);
        atomicAdd(&g_feanum[sn * CC + tid], s);
    }
    float* amp = g_avgm + (size_t)sn * HWP + px;
    float* mmp = g_maxm + (size_t)sn * HWP + px;
    *(float4*)amp = am1; *(float4*)(amp + 4) = am2;
    *(float4*)mmp = mm1; *(float4*)(mmp + 4) = mm2;
}

// ---- K4: gate = sigmoid(LN(fea @ convb_w^T)) ----
__global__ void k4_gate(const float* __restrict__ convb_w,
                        const float* __restrict__ ln_g, const float* __restrict__ ln_b) {
    int n = blockIdx.x, me = blockIdx.y, sn = me * NB + n;
    int t = threadIdx.x;  // 64
    __shared__ float sf[64];
    __shared__ float red[64];
    float Z = g_Z[sn];
    sf[t] = g_feanum[sn * CC + t] / Z;
    __syncthreads();
    float v = 0.f;
    for (int c = 0; c < 64; c++) v = fmaf(convb_w[t * 64 + c], sf[c], v);
    red[t] = v; __syncthreads();
    for (int d = 32; d; d >>= 1) { if (t < d) red[t] += red[t + d]; __syncthreads(); }
    float mu = red[0] * (1.f / 64.f); __syncthreads();
    float dv = v - mu;
    red[t] = dv * dv; __syncthreads();
    for (int d = 32; d; d >>= 1) { if (t < d) red[t] += red[t + d]; __syncthreads(); }
    float var = red[0] * (1.f / 64.f);
    float nrm = fmaf(dv * rsqrtf(var + EPSV), ln_g[t], ln_b[t]);
    g_gate[sn * CC + t] = 1.f / (1.f + __expf(-nrm));
}

// ---- K5: half conv_block from precomputed avgm/maxm + gated residual output ----
__global__ void __launch_bounds__(256) k5_out(
    const float* __restrict__ rgb, const float* __restrict__ ir,
    const float* __restrict__ half_w, const float* __restrict__ half_g,
    const float* __restrict__ half_b, const float* __restrict__ half_m,
    const float* __restrict__ half_vv, float* __restrict__ out)
{
    int me = blockIdx.z, n = blockIdx.y, p0 = blockIdx.x * 1024;
    int sn = me * NB + n;
    int tid = threadIdx.x;
    __shared__ float sG[64];
    if (tid < 64) sG[tid] = g_gate[sn * CC + tid];
    __syncthreads();
    float h0 = half_w[0], h1 = half_w[1];
    float hsc = half_g[0] * rsqrtf(half_vv[0] + EPSV);
    float hsh = half_b[0] - half_m[0] * hsc;

    int px = p0 + tid * 4;
    float4 am = *(const float4*)(g_avgm + (size_t)sn * HWP + px);
    float4 mm = *(const float4*)(g_maxm + (size_t)sn * HWP + px);
    float4 h;
    h.x = siluf(fmaf(fmaf(h0, am.x, h1 * mm.x), hsc, hsh));
    h.y = siluf(fmaf(fmaf(h0, am.y, h1 * mm.y), hsc, hsh));
    h.z = siluf(fmaf(fmaf(h0, am.z, h1 * mm.z), hsc, hsh));
    h.w = siluf(fmaf(fmaf(h0, am.w, h1 * mm.w), hsc, hsh));

    size_t pq = (size_t)px >> 2;
    const float4* xme = (const float4*)((me ? ir : rgb) + (size_t)n * CC * HWP);
    float4* ob = (float4*)(out + (size_t)sn * CC * HWP);
#pragma unroll 8
    for (int c = 0; c < 64; c++) {
        float4 x4 = xme[(size_t)c * (HWP / 4) + pq];
        float g = sG[c];
        float4 o4;
        o4.x = fmaf(g, h.x, x4.x);
        o4.y = fmaf(g, h.y, x4.y);
        o4.z = fmaf(g, h.z, x4.z);
        o4.w = fmaf(g, h.w, x4.w);
        ob[(size_t)c * (HWP / 4) + pq] = o4;
    }
}

extern "C" void kernel_launch(void* const* d_in, const int* in_sizes, int n_in,
                              void* d_out, int out_size) {
    const float* rgb     = (const float*)d_in[0];
    const float* ir      = (const float*)d_in[1];
    const float* conv_w  = (const float*)d_in[2];
    const float* conv_b  = (const float*)d_in[3];
    const float* key_w   = (const float*)d_in[4];
    const float* key_g   = (const float*)d_in[5];
    const float* key_b   = (const float*)d_in[6];
    const float* key_m   = (const float*)d_in[7];
    const float* key_v   = (const float*)d_in[8];
    const float* val_w   = (const float*)d_in[9];
    const float* val_g   = (const float*)d_in[10];
    const float* val_b   = (const float*)d_in[11];
    const float* val_m   = (const float*)d_in[12];
    const float* val_v   = (const float*)d_in[13];
    const float* convb_w = (const float*)d_in[14];
    const float* half_w  = (const float*)d_in[15];
    const float* half_g  = (const float*)d_in[16];
    const float* half_b  = (const float*)d_in[17];
    const float* half_m  = (const float*)d_in[18];
    const float* half_v  = (const float*)d_in[19];
    const float* ln_g    = (const float*)d_in[20];
    const float* ln_b    = (const float*)d_in[21];
    float* out = (float*)d_out;

    const int smem1 = (128 * SWH + 32 * SXH) * 4 + 192 * 4;  // ~53KB
    cudaFuncSetAttribute(k1_main, cudaFuncAttributeMaxDynamicSharedMemorySize, smem1);

    k0_init<<<1, 1024>>>();
    k1_main<<<dim3(HWP / TP1, NB, SIDES), 512, smem1>>>(
        rgb, ir, conv_w, key_w, val_w, val_g, val_b, val_m, val_v,
        key_g, key_b, key_m, key_v);
    k2_avgmax<<<dim3(NB, SIDES), 64>>>(conv_w, conv_b);
    k3_fea<<<dim3(HWP / 1024, NB, SIDES), 128>>>();
    k4_gate<<<dim3(NB, SIDES), 64>>>(convb_w, ln_g, ln_b);
    k5_out<<<dim3(HWP / 1024, NB, SIDES), 256>>>(
        rgb, ir, half_w, half_g, half_b, half_m, half_v, out);
}